// round 1
// baseline (speedup 1.0000x reference)
#include <cuda_runtime.h>
#include <math.h>

// Problem constants
#define Bb   8
#define Cc   256
#define Nn   2304          // H*W = 48*48
#define Mtot (Bb*Nn)       // 18432
#define EPSf 1e-5f

// ---------------------------------------------------------------------------
// Scratch (device globals — no runtime allocation allowed)
// ---------------------------------------------------------------------------
__device__ float g_q[2][Mtot*Cc];            // [r/i][ (b*Nn+n)*Cc + c ]
__device__ float g_k[2][Mtot*Cc];
__device__ float g_v[2][Mtot*Cc];
__device__ float g_attn[(size_t)Bb*Nn*Nn];   // [b][n][m]
__device__ float g_outT[2][Bb*Cc*Nn];        // [r/i][b][c][n]  (transposed for BN)
__device__ float g_mean[2][Cc];
__device__ float g_rstd[2][Cc];

// ---------------------------------------------------------------------------
// Kernel 1: complex linear projection   y = x @ W^T + b  (complex)
//   x given as [b, c, n] (channel-major);  y written as [(b*Nn+n), c]
//   64x64 output tile, K-tile 16, 4x4 microtile, both real+imag fused.
//   W template arg selects q/k/v destination.
// ---------------------------------------------------------------------------
template<int WSEL>
__global__ void __launch_bounds__(256) k_clinear(
    const float* __restrict__ xr, const float* __restrict__ xi,
    const float* __restrict__ wr, const float* __restrict__ wi,
    const float* __restrict__ br, const float* __restrict__ bi)
{
    float* yr = (WSEL==0) ? g_q[0] : (WSEL==1) ? g_k[0] : g_v[0];
    float* yi = (WSEL==0) ? g_q[1] : (WSEL==1) ? g_k[1] : g_v[1];

    __shared__ float Ar[16][64], Ai[16][64];
    __shared__ float Wr[16][65], Wi[16][65];

    const int tx = threadIdx.x, ty = threadIdx.y;
    const int tid = ty*16 + tx;
    const int m0 = blockIdx.x * 64;       // row block over Mtot (one batch per tile)
    const int d0 = blockIdx.y * 64;       // output channel block
    const int b  = m0 / Nn;
    const int n0 = m0 - b*Nn;

    float accr[4][4] = {}, acci[4][4] = {};

    for (int kt = 0; kt < Cc/16; ++kt) {
        const int ck = kt*16;
        #pragma unroll
        for (int t = 0; t < 4; ++t) {           // x tile: 16(c) x 64(n), coalesced in n
            int idx = tid + 256*t;
            int k = idx >> 6, row = idx & 63;
            int g = b*Cc*Nn + (ck+k)*Nn + n0 + row;
            Ar[k][row] = xr[g];
            Ai[k][row] = xi[g];
        }
        #pragma unroll
        for (int t = 0; t < 4; ++t) {           // w tile: 16(c) x 64(d), coalesced in c
            int idx = tid + 256*t;
            int k = idx & 15, dd = idx >> 4;
            int g = (d0+dd)*Cc + ck + k;
            Wr[k][dd] = wr[g];
            Wi[k][dd] = wi[g];
        }
        __syncthreads();
        #pragma unroll
        for (int k = 0; k < 16; ++k) {
            float axr[4], axi[4], wxr[4], wxi[4];
            #pragma unroll
            for (int j = 0; j < 4; ++j) { axr[j] = Ar[k][ty+16*j]; axi[j] = Ai[k][ty+16*j]; }
            #pragma unroll
            for (int i = 0; i < 4; ++i) { wxr[i] = Wr[k][tx+16*i]; wxi[i] = Wi[k][tx+16*i]; }
            #pragma unroll
            for (int j = 0; j < 4; ++j)
                #pragma unroll
                for (int i = 0; i < 4; ++i) {
                    accr[j][i] += axr[j]*wxr[i] - axi[j]*wxi[i];
                    acci[j][i] += axr[j]*wxi[i] + axi[j]*wxr[i];
                }
        }
        __syncthreads();
    }

    #pragma unroll
    for (int i = 0; i < 4; ++i) {
        const int d = d0 + tx + 16*i;
        const float brd = br[d], bid = bi[d];
        #pragma unroll
        for (int j = 0; j < 4; ++j) {
            const int m = m0 + ty + 16*j;
            yr[m*Cc + d] = accr[j][i] + brd;   // coalesced along d
            yi[m*Cc + d] = acci[j][i] + bid;
        }
    }
}

// ---------------------------------------------------------------------------
// Kernel 2: attention scores  S[b,n,m] = (Qr.Kr + Qi.Ki)/sqrt(C)
//   GEMM-NT per batch, effective K = 2*Cc = 512.
// ---------------------------------------------------------------------------
__global__ void __launch_bounds__(256) k_scores()
{
    __shared__ float Qr[64][17], Qi[64][17], Kr[64][17], Ki[64][17];

    const int tx = threadIdx.x, ty = threadIdx.y;
    const int tid = ty*16 + tx;
    const int m0 = blockIdx.x * 64;  // key block
    const int n0 = blockIdx.y * 64;  // query block
    const int b  = blockIdx.z;

    const float* qr = &g_q[0][(size_t)b*Nn*Cc];
    const float* qi = &g_q[1][(size_t)b*Nn*Cc];
    const float* kr = &g_k[0][(size_t)b*Nn*Cc];
    const float* ki = &g_k[1][(size_t)b*Nn*Cc];

    float acc[4][4] = {};

    for (int kt = 0; kt < Cc/16; ++kt) {
        const int ck = kt*16;
        #pragma unroll
        for (int t = 0; t < 4; ++t) {       // 64 rows x 16 c, coalesced in c
            int idx = tid + 256*t;
            int k = idx & 15, row = idx >> 4;
            Qr[row][k] = qr[(n0+row)*Cc + ck + k];
            Qi[row][k] = qi[(n0+row)*Cc + ck + k];
            Kr[row][k] = kr[(m0+row)*Cc + ck + k];
            Ki[row][k] = ki[(m0+row)*Cc + ck + k];
        }
        __syncthreads();
        #pragma unroll
        for (int k = 0; k < 16; ++k) {
            float qvr[4], qvi[4], kvr[4], kvi[4];
            #pragma unroll
            for (int j = 0; j < 4; ++j) { qvr[j] = Qr[ty+16*j][k]; qvi[j] = Qi[ty+16*j][k]; }
            #pragma unroll
            for (int i = 0; i < 4; ++i) { kvr[i] = Kr[tx+16*i][k]; kvi[i] = Ki[tx+16*i][k]; }
            #pragma unroll
            for (int j = 0; j < 4; ++j)
                #pragma unroll
                for (int i = 0; i < 4; ++i)
                    acc[j][i] += qvr[j]*kvr[i] + qvi[j]*kvi[i];
        }
        __syncthreads();
    }

    const float inv_scale = 1.0f/16.0f;   // 1/sqrt(256)
    #pragma unroll
    for (int j = 0; j < 4; ++j) {
        const size_t rowbase = (size_t)b*Nn*Nn + (size_t)(n0 + ty + 16*j)*Nn;
        #pragma unroll
        for (int i = 0; i < 4; ++i)
            g_attn[rowbase + m0 + tx + 16*i] = acc[j][i] * inv_scale;  // coalesced in m
    }
}

// ---------------------------------------------------------------------------
// Kernel 3: row softmax over m (row length 2304, one block per row)
// ---------------------------------------------------------------------------
__global__ void __launch_bounds__(256) k_softmax()
{
    const size_t base = (size_t)blockIdx.x * Nn;
    const int tid = threadIdx.x;
    __shared__ float red[256];

    float v[9];
    float mx = -1e30f;
    #pragma unroll
    for (int i = 0; i < 9; ++i) { v[i] = g_attn[base + tid + 256*i]; mx = fmaxf(mx, v[i]); }

    red[tid] = mx; __syncthreads();
    #pragma unroll
    for (int s = 128; s > 0; s >>= 1) {
        if (tid < s) red[tid] = fmaxf(red[tid], red[tid+s]);
        __syncthreads();
    }
    mx = red[0]; __syncthreads();

    float sum = 0.f;
    #pragma unroll
    for (int i = 0; i < 9; ++i) { v[i] = __expf(v[i] - mx); sum += v[i]; }

    red[tid] = sum; __syncthreads();
    #pragma unroll
    for (int s = 128; s > 0; s >>= 1) {
        if (tid < s) red[tid] += red[tid+s];
        __syncthreads();
    }
    const float inv = 1.f / red[0];
    #pragma unroll
    for (int i = 0; i < 9; ++i) g_attn[base + tid + 256*i] = v[i] * inv;
}

// ---------------------------------------------------------------------------
// Kernel 4: out = A @ V (real and imag simultaneously; A shared)
//   writes transposed [b, c, n] so BN stage is unit-stride
// ---------------------------------------------------------------------------
__global__ void __launch_bounds__(256) k_av()
{
    __shared__ float As[64][17];
    __shared__ float Vr[16][64], Vi[16][64];

    const int tx = threadIdx.x, ty = threadIdx.y;
    const int tid = ty*16 + tx;
    const int n0 = blockIdx.x * 64;   // query block
    const int d0 = blockIdx.y * 64;   // channel block
    const int b  = blockIdx.z;

    const float* A  = g_attn + (size_t)b*Nn*Nn;
    const float* vr = &g_v[0][(size_t)b*Nn*Cc];
    const float* vi = &g_v[1][(size_t)b*Nn*Cc];

    float accr[4][4] = {}, acci[4][4] = {};

    for (int kt = 0; kt < Nn/16; ++kt) {        // 144 K-tiles
        const int mk = kt*16;
        #pragma unroll
        for (int t = 0; t < 4; ++t) {           // A: 64(n) x 16(m), coalesced in m
            int idx = tid + 256*t;
            int k = idx & 15, row = idx >> 4;
            As[row][k] = A[(size_t)(n0+row)*Nn + mk + k];
        }
        #pragma unroll
        for (int t = 0; t < 4; ++t) {           // V: 16(m) x 64(d), coalesced in d
            int idx = tid + 256*t;
            int k = idx >> 6, dd = idx & 63;
            int g = (mk+k)*Cc + d0 + dd;
            Vr[k][dd] = vr[g];
            Vi[k][dd] = vi[g];
        }
        __syncthreads();
        #pragma unroll
        for (int k = 0; k < 16; ++k) {
            float a[4], vvr[4], vvi[4];
            #pragma unroll
            for (int i = 0; i < 4; ++i) a[i] = As[tx+16*i][k];
            #pragma unroll
            for (int j = 0; j < 4; ++j) { vvr[j] = Vr[k][ty+16*j]; vvi[j] = Vi[k][ty+16*j]; }
            #pragma unroll
            for (int i = 0; i < 4; ++i)
                #pragma unroll
                for (int j = 0; j < 4; ++j) {
                    accr[i][j] += a[i]*vvr[j];
                    acci[i][j] += a[i]*vvi[j];
                }
        }
        __syncthreads();
    }

    #pragma unroll
    for (int j = 0; j < 4; ++j) {
        const int d = d0 + ty + 16*j;
        const size_t basep = (size_t)b*Cc*Nn + (size_t)d*Nn;
        #pragma unroll
        for (int i = 0; i < 4; ++i) {
            const int n = n0 + tx + 16*i;
            g_outT[0][basep + n] = accr[i][j];   // coalesced in n
            g_outT[1][basep + n] = acci[i][j];
        }
    }
}

// ---------------------------------------------------------------------------
// Kernel 5: per-channel batch stats of z = x + gamma*out  (biased var)
//   one block per (channel, part); unit-stride reads
// ---------------------------------------------------------------------------
__global__ void __launch_bounds__(256) k_bnstats(
    const float* __restrict__ xr, const float* __restrict__ xi,
    const float* __restrict__ gamma)
{
    const int c = blockIdx.x, p = blockIdx.y;
    const int tid = threadIdx.x;
    const float* x = p ? xi : xr;
    const float* o = g_outT[p];
    const float g = gamma[0];

    float s = 0.f, ss = 0.f;
    for (int b = 0; b < Bb; ++b) {
        const int base = b*Cc*Nn + c*Nn;
        for (int n = tid; n < Nn; n += 256) {
            float z = x[base+n] + g*o[base+n];
            s  += z;
            ss += z*z;
        }
    }
    __shared__ float rs[256], rss[256];
    rs[tid] = s; rss[tid] = ss; __syncthreads();
    #pragma unroll
    for (int st = 128; st > 0; st >>= 1) {
        if (tid < st) { rs[tid] += rs[tid+st]; rss[tid] += rss[tid+st]; }
        __syncthreads();
    }
    if (tid == 0) {
        const float inv_cnt = 1.f / (float)Mtot;
        float mean = rs[0] * inv_cnt;
        float var  = rss[0] * inv_cnt - mean*mean;
        g_mean[p][c] = mean;
        g_rstd[p][c] = rsqrtf(var + EPSf);
    }
}

// ---------------------------------------------------------------------------
// Kernel 6: normalize + affine, write final [2,B,C,H,W]
// ---------------------------------------------------------------------------
__global__ void __launch_bounds__(256) k_bnapply(
    const float* __restrict__ xr, const float* __restrict__ xi,
    const float* __restrict__ gamma,
    const float* __restrict__ bnwr, const float* __restrict__ bnbr,
    const float* __restrict__ bnwi, const float* __restrict__ bnbi,
    float* __restrict__ out)
{
    const int idx = blockIdx.x*256 + threadIdx.x;       // over 2*Bb*Cc*Nn
    const int half = Bb*Cc*Nn;
    const int p = idx / half;
    const int rem = idx - p*half;
    const int c = (rem / Nn) % Cc;

    const float* x = p ? xi : xr;
    const float g = gamma[0];
    const float z = x[rem] + g*g_outT[p][rem];
    const float w = p ? bnwi[c] : bnwr[c];
    const float bia = p ? bnbi[c] : bnbr[c];
    out[idx] = (z - g_mean[p][c]) * g_rstd[p][c] * w + bia;
}

// ---------------------------------------------------------------------------
// Launch
// ---------------------------------------------------------------------------
extern "C" void kernel_launch(void* const* d_in, const int* in_sizes, int n_in,
                              void* d_out, int out_size)
{
    const float* xr   = (const float*)d_in[0];
    const float* xi   = (const float*)d_in[1];
    const float* q_wr = (const float*)d_in[2];
    const float* q_wi = (const float*)d_in[3];
    const float* q_br = (const float*)d_in[4];
    const float* q_bi = (const float*)d_in[5];
    const float* k_wr = (const float*)d_in[6];
    const float* k_wi = (const float*)d_in[7];
    const float* k_br = (const float*)d_in[8];
    const float* k_bi = (const float*)d_in[9];
    const float* v_wr = (const float*)d_in[10];
    const float* v_wi = (const float*)d_in[11];
    const float* v_br = (const float*)d_in[12];
    const float* v_bi = (const float*)d_in[13];
    const float* gamma= (const float*)d_in[14];
    const float* bnwr = (const float*)d_in[15];
    const float* bnbr = (const float*)d_in[16];
    const float* bnwi = (const float*)d_in[17];
    const float* bnbi = (const float*)d_in[18];
    float* out = (float*)d_out;

    const dim3 blk(16, 16);

    // Q/K/V complex projections
    k_clinear<0><<<dim3(Mtot/64, Cc/64), blk>>>(xr, xi, q_wr, q_wi, q_br, q_bi);
    k_clinear<1><<<dim3(Mtot/64, Cc/64), blk>>>(xr, xi, k_wr, k_wi, k_br, k_bi);
    k_clinear<2><<<dim3(Mtot/64, Cc/64), blk>>>(xr, xi, v_wr, v_wi, v_br, v_bi);

    // Attention scores
    k_scores<<<dim3(Nn/64, Nn/64, Bb), blk>>>();

    // Softmax
    k_softmax<<<Mtot, 256>>>();

    // A @ V
    k_av<<<dim3(Nn/64, Cc/64, Bb), blk>>>();

    // BatchNorm (batch statistics) on residual
    k_bnstats<<<dim3(Cc, 2), 256>>>(xr, xi, gamma);
    k_bnapply<<<(2*Bb*Cc*Nn)/256, 256>>>(xr, xi, gamma, bnwr, bnbr, bnwi, bnbi, out);
}

// round 2
// speedup vs baseline: 2.3421x; 2.3421x over previous
#include <cuda_runtime.h>
#include <math.h>
#include <stdint.h>

#define Bb   8
#define Cc   256
#define Nn   2304
#define Mtot (Bb*Nn)
#define EPSf 1e-5f

// ---------------------------------------------------------------------------
// Scratch
// ---------------------------------------------------------------------------
__device__ float g_q[2][Mtot*Cc];
__device__ float g_k[2][Mtot*Cc];
__device__ float g_v[2][Mtot*Cc];
__device__ float g_attn[(size_t)Bb*Nn*Nn];
__device__ float g_outT[2][Bb*Cc*Nn];
__device__ float g_mean[2][Cc];
__device__ float g_rstd[2][Cc];

// ---------------------------------------------------------------------------
// tf32 helpers
// ---------------------------------------------------------------------------
__device__ __forceinline__ uint32_t f2tf(float f){
    uint32_t u; asm("cvt.rna.tf32.f32 %0,%1;" : "=r"(u) : "f"(f)); return u;
}
__device__ __forceinline__ void mma8(float* d, const uint32_t* a, const uint32_t* b){
    asm volatile("mma.sync.aligned.m16n8k8.row.col.f32.tf32.tf32.f32 "
        "{%0,%1,%2,%3}, {%4,%5,%6,%7}, {%8,%9}, {%0,%1,%2,%3};"
        : "+f"(d[0]),"+f"(d[1]),"+f"(d[2]),"+f"(d[3])
        : "r"(a[0]),"r"(a[1]),"r"(a[2]),"r"(a[3]),"r"(b[0]),"r"(b[1]));
}

// ---------------------------------------------------------------------------
// Kernel 1: complex projection  (yr,yi)[m,d] = (Xr+iXi)(Wr+iWi)^T + b
//   Block tile 128m x 64d, warps 4(m)x2(d), warp tile 32x32. K-tile 16.
// ---------------------------------------------------------------------------
template<int WSEL>
__global__ void __launch_bounds__(256) k_proj(
    const float* __restrict__ xr, const float* __restrict__ xi,
    const float* __restrict__ wr, const float* __restrict__ wi,
    const float* __restrict__ brv, const float* __restrict__ biv)
{
    float* yr = (WSEL==0)?g_q[0]:(WSEL==1)?g_k[0]:g_v[0];
    float* yi = (WSEL==0)?g_q[1]:(WSEL==1)?g_k[1]:g_v[1];

    __shared__ uint32_t sXr[128][17], sXi[128][17];
    __shared__ uint32_t sWr[64][17],  sWi[64][17];

    const int tid = threadIdx.x;
    const int w = tid >> 5, lane = tid & 31;
    const int gr = lane >> 2, tg = lane & 3;
    const int wm = w & 3, wn = w >> 2;
    const int m0 = blockIdx.x * 128;
    const int d0 = blockIdx.y * 64;
    const int b  = m0 / Nn;
    const int n0 = m0 - b*Nn;

    float accr[2][4][4], acci[2][4][4];
    #pragma unroll
    for (int mf=0; mf<2; ++mf)
        #pragma unroll
        for (int nf=0; nf<4; ++nf)
            #pragma unroll
            for (int e=0; e<4; ++e) { accr[mf][nf][e]=0.f; acci[mf][nf][e]=0.f; }

    for (int kt = 0; kt < Cc/16; ++kt) {
        const int ck = kt*16;
        #pragma unroll
        for (int t=0; t<8; ++t) {        // X: [c][n] gmem, coalesced in n
            int idx = tid + 256*t; int r = idx & 127, kk = idx >> 7;
            int g = b*Cc*Nn + (ck+kk)*Nn + n0 + r;
            sXr[r][kk] = f2tf(xr[g]);
            sXi[r][kk] = f2tf(xi[g]);
        }
        #pragma unroll
        for (int t=0; t<4; ++t) {        // W: [d][c] gmem, coalesced in c
            int idx = tid + 256*t; int kk = idx & 15, dd = idx >> 4;
            int g = (d0+dd)*Cc + ck + kk;
            sWr[dd][kk] = f2tf(wr[g]);
            sWi[dd][kk] = f2tf(wi[g]);
        }
        __syncthreads();
        #pragma unroll
        for (int ks=0; ks<16; ks+=8) {
            uint32_t ar[2][4], ai[2][4];
            #pragma unroll
            for (int mf=0; mf<2; ++mf) {
                int rb = wm*32 + mf*16;
                ar[mf][0]=sXr[rb+gr  ][ks+tg  ]; ar[mf][1]=sXr[rb+gr+8][ks+tg  ];
                ar[mf][2]=sXr[rb+gr  ][ks+tg+4]; ar[mf][3]=sXr[rb+gr+8][ks+tg+4];
                ai[mf][0]=sXi[rb+gr  ][ks+tg  ]; ai[mf][1]=sXi[rb+gr+8][ks+tg  ];
                ai[mf][2]=sXi[rb+gr  ][ks+tg+4]; ai[mf][3]=sXi[rb+gr+8][ks+tg+4];
            }
            #pragma unroll
            for (int nf=0; nf<4; ++nf) {
                int cb = wn*32 + nf*8;
                uint32_t bwr[2] = { sWr[cb+gr][ks+tg], sWr[cb+gr][ks+tg+4] };
                uint32_t bwi[2] = { sWi[cb+gr][ks+tg], sWi[cb+gr][ks+tg+4] };
                #pragma unroll
                for (int mf=0; mf<2; ++mf) {
                    uint32_t ain[4] = { ai[mf][0]^0x80000000u, ai[mf][1]^0x80000000u,
                                        ai[mf][2]^0x80000000u, ai[mf][3]^0x80000000u };
                    mma8(accr[mf][nf], ar[mf], bwr);   //  Xr*Wr
                    mma8(accr[mf][nf], ain,    bwi);   // -Xi*Wi
                    mma8(acci[mf][nf], ar[mf], bwi);   //  Xr*Wi
                    mma8(acci[mf][nf], ai[mf], bwr);   //  Xi*Wr
                }
            }
        }
        __syncthreads();
    }

    #pragma unroll
    for (int mf=0; mf<2; ++mf) {
        const int row0 = m0 + wm*32 + mf*16 + gr;
        #pragma unroll
        for (int nf=0; nf<4; ++nf) {
            const int col0 = d0 + wn*32 + nf*8 + 2*tg;
            const float b0r = brv[col0], b1r = brv[col0+1];
            const float b0i = biv[col0], b1i = biv[col0+1];
            yr[(size_t)row0*Cc + col0  ]     = accr[mf][nf][0] + b0r;
            yr[(size_t)row0*Cc + col0+1]     = accr[mf][nf][1] + b1r;
            yr[(size_t)(row0+8)*Cc + col0  ] = accr[mf][nf][2] + b0r;
            yr[(size_t)(row0+8)*Cc + col0+1] = accr[mf][nf][3] + b1r;
            yi[(size_t)row0*Cc + col0  ]     = acci[mf][nf][0] + b0i;
            yi[(size_t)row0*Cc + col0+1]     = acci[mf][nf][1] + b1i;
            yi[(size_t)(row0+8)*Cc + col0  ] = acci[mf][nf][2] + b0i;
            yi[(size_t)(row0+8)*Cc + col0+1] = acci[mf][nf][3] + b1i;
        }
    }
}

// ---------------------------------------------------------------------------
// Kernel 2: scores  S = (Qr Kr^T + Qi Ki^T)/16
//   Block 128n x 128m, warps 2(n)x4(m), warp tile 64x32. K-tile 16.
// ---------------------------------------------------------------------------
__global__ void __launch_bounds__(256) k_scores()
{
    __shared__ uint32_t sQr[128][17], sQi[128][17];
    __shared__ uint32_t sKr[128][17], sKi[128][17];

    const int tid = threadIdx.x;
    const int w = tid >> 5, lane = tid & 31;
    const int gr = lane >> 2, tg = lane & 3;
    const int wrow = w & 1, wcol = w >> 1;
    const int m0 = blockIdx.x * 128;
    const int n0 = blockIdx.y * 128;
    const int b  = blockIdx.z;

    const float* qr = &g_q[0][(size_t)b*Nn*Cc];
    const float* qi = &g_q[1][(size_t)b*Nn*Cc];
    const float* kr = &g_k[0][(size_t)b*Nn*Cc];
    const float* ki = &g_k[1][(size_t)b*Nn*Cc];

    float acc[4][4][4];
    #pragma unroll
    for (int mf=0; mf<4; ++mf)
        #pragma unroll
        for (int nf=0; nf<4; ++nf)
            #pragma unroll
            for (int e=0; e<4; ++e) acc[mf][nf][e]=0.f;

    for (int kt = 0; kt < Cc/16; ++kt) {
        const int ck = kt*16;
        #pragma unroll
        for (int t=0; t<8; ++t) {
            int idx = tid + 256*t; int kk = idx & 15, r = idx >> 4;
            sQr[r][kk] = f2tf(qr[(size_t)(n0+r)*Cc + ck + kk]);
            sQi[r][kk] = f2tf(qi[(size_t)(n0+r)*Cc + ck + kk]);
            sKr[r][kk] = f2tf(kr[(size_t)(m0+r)*Cc + ck + kk]);
            sKi[r][kk] = f2tf(ki[(size_t)(m0+r)*Cc + ck + kk]);
        }
        __syncthreads();
        #pragma unroll
        for (int ks=0; ks<16; ks+=8) {
            // real pass
            {
                uint32_t a[4][4];
                #pragma unroll
                for (int mf=0; mf<4; ++mf) {
                    int rb = wrow*64 + mf*16;
                    a[mf][0]=sQr[rb+gr  ][ks+tg  ]; a[mf][1]=sQr[rb+gr+8][ks+tg  ];
                    a[mf][2]=sQr[rb+gr  ][ks+tg+4]; a[mf][3]=sQr[rb+gr+8][ks+tg+4];
                }
                #pragma unroll
                for (int nf=0; nf<4; ++nf) {
                    int cb = wcol*32 + nf*8;
                    uint32_t bb[2] = { sKr[cb+gr][ks+tg], sKr[cb+gr][ks+tg+4] };
                    #pragma unroll
                    for (int mf=0; mf<4; ++mf) mma8(acc[mf][nf], a[mf], bb);
                }
            }
            // imag pass
            {
                uint32_t a[4][4];
                #pragma unroll
                for (int mf=0; mf<4; ++mf) {
                    int rb = wrow*64 + mf*16;
                    a[mf][0]=sQi[rb+gr  ][ks+tg  ]; a[mf][1]=sQi[rb+gr+8][ks+tg  ];
                    a[mf][2]=sQi[rb+gr  ][ks+tg+4]; a[mf][3]=sQi[rb+gr+8][ks+tg+4];
                }
                #pragma unroll
                for (int nf=0; nf<4; ++nf) {
                    int cb = wcol*32 + nf*8;
                    uint32_t bb[2] = { sKi[cb+gr][ks+tg], sKi[cb+gr][ks+tg+4] };
                    #pragma unroll
                    for (int mf=0; mf<4; ++mf) mma8(acc[mf][nf], a[mf], bb);
                }
            }
        }
        __syncthreads();
    }

    const float sc = 1.0f/16.0f;
    #pragma unroll
    for (int mf=0; mf<4; ++mf) {
        const int row0 = n0 + wrow*64 + mf*16 + gr;
        const size_t r0b = (size_t)b*Nn*Nn + (size_t)row0*Nn;
        const size_t r1b = r0b + (size_t)8*Nn;
        #pragma unroll
        for (int nf=0; nf<4; ++nf) {
            const int col0 = m0 + wcol*32 + nf*8 + 2*tg;
            g_attn[r0b + col0  ] = acc[mf][nf][0]*sc;
            g_attn[r0b + col0+1] = acc[mf][nf][1]*sc;
            g_attn[r1b + col0  ] = acc[mf][nf][2]*sc;
            g_attn[r1b + col0+1] = acc[mf][nf][3]*sc;
        }
    }
}

// ---------------------------------------------------------------------------
// Kernel 3: softmax (unchanged)
// ---------------------------------------------------------------------------
__global__ void __launch_bounds__(256) k_softmax()
{
    const size_t base = (size_t)blockIdx.x * Nn;
    const int tid = threadIdx.x;
    __shared__ float red[256];

    float v[9];
    float mx = -1e30f;
    #pragma unroll
    for (int i = 0; i < 9; ++i) { v[i] = g_attn[base + tid + 256*i]; mx = fmaxf(mx, v[i]); }

    red[tid] = mx; __syncthreads();
    #pragma unroll
    for (int s = 128; s > 0; s >>= 1) {
        if (tid < s) red[tid] = fmaxf(red[tid], red[tid+s]);
        __syncthreads();
    }
    mx = red[0]; __syncthreads();

    float sum = 0.f;
    #pragma unroll
    for (int i = 0; i < 9; ++i) { v[i] = __expf(v[i] - mx); sum += v[i]; }

    red[tid] = sum; __syncthreads();
    #pragma unroll
    for (int s = 128; s > 0; s >>= 1) {
        if (tid < s) red[tid] += red[tid+s];
        __syncthreads();
    }
    const float inv = 1.f / red[0];
    #pragma unroll
    for (int i = 0; i < 9; ++i) g_attn[base + tid + 256*i] = v[i] * inv;
}

// ---------------------------------------------------------------------------
// Kernel 4: AV  out[n,d] = A@Vr, A@Vi ; stores transposed [d][n] via smem
//   Block 128n x 64d, warps 4(n)x2(d), warp tile 32x32. K-tile 16 over m.
// ---------------------------------------------------------------------------
__global__ void __launch_bounds__(256) k_av()
{
    __shared__ __align__(16) unsigned char raw[64*129*4];  // 33 KB union
    uint32_t (*sA )[17] = (uint32_t(*)[17]) raw;                 // 8704 B
    uint32_t (*sVr)[65] = (uint32_t(*)[65])(raw + 8704);         // 4160 B
    uint32_t (*sVi)[65] = (uint32_t(*)[65])(raw + 12864);        // 4160 B
    float    (*stage)[129] = (float(*)[129]) raw;                // epilogue

    const int tid = threadIdx.x;
    const int w = tid >> 5, lane = tid & 31;
    const int gr = lane >> 2, tg = lane & 3;
    const int wm = w & 3, wn = w >> 2;
    const int n0 = blockIdx.x * 128;
    const int d0 = blockIdx.y * 64;
    const int b  = blockIdx.z;

    const float* A  = g_attn + (size_t)b*Nn*Nn;
    const float* vr = &g_v[0][(size_t)b*Nn*Cc];
    const float* vi = &g_v[1][(size_t)b*Nn*Cc];

    float accr[2][4][4], acci[2][4][4];
    #pragma unroll
    for (int mf=0; mf<2; ++mf)
        #pragma unroll
        for (int nf=0; nf<4; ++nf)
            #pragma unroll
            for (int e=0; e<4; ++e) { accr[mf][nf][e]=0.f; acci[mf][nf][e]=0.f; }

    for (int kt = 0; kt < Nn/16; ++kt) {
        const int mk = kt*16;
        #pragma unroll
        for (int t=0; t<8; ++t) {
            int idx = tid + 256*t; int kk = idx & 15, r = idx >> 4;
            sA[r][kk] = f2tf(A[(size_t)(n0+r)*Nn + mk + kk]);
        }
        #pragma unroll
        for (int t=0; t<4; ++t) {
            int idx = tid + 256*t; int dd = idx & 63, k = idx >> 6;
            sVr[k][dd] = f2tf(vr[(size_t)(mk+k)*Cc + d0 + dd]);
            sVi[k][dd] = f2tf(vi[(size_t)(mk+k)*Cc + d0 + dd]);
        }
        __syncthreads();
        #pragma unroll
        for (int ks=0; ks<16; ks+=8) {
            uint32_t a[2][4];
            #pragma unroll
            for (int mf=0; mf<2; ++mf) {
                int rb = wm*32 + mf*16;
                a[mf][0]=sA[rb+gr  ][ks+tg  ]; a[mf][1]=sA[rb+gr+8][ks+tg  ];
                a[mf][2]=sA[rb+gr  ][ks+tg+4]; a[mf][3]=sA[rb+gr+8][ks+tg+4];
            }
            #pragma unroll
            for (int nf=0; nf<4; ++nf) {
                int cb = wn*32 + nf*8;
                uint32_t bvr[2] = { sVr[ks+tg][cb+gr], sVr[ks+tg+4][cb+gr] };
                uint32_t bvi[2] = { sVi[ks+tg][cb+gr], sVi[ks+tg+4][cb+gr] };
                #pragma unroll
                for (int mf=0; mf<2; ++mf) {
                    mma8(accr[mf][nf], a[mf], bvr);
                    mma8(acci[mf][nf], a[mf], bvi);
                }
            }
        }
        __syncthreads();
    }

    // transpose epilogue: stage [d_local][n_local] then coalesced write along n
    const size_t basep = (size_t)b*Cc*Nn + (size_t)d0*Nn + n0;
    #pragma unroll
    for (int p=0; p<2; ++p) {
        #pragma unroll
        for (int mf=0; mf<2; ++mf) {
            int rl = wm*32 + mf*16 + gr;
            #pragma unroll
            for (int nf=0; nf<4; ++nf) {
                int cl = wn*32 + nf*8 + 2*tg;
                float* acc = p ? acci[mf][nf] : accr[mf][nf];
                stage[cl  ][rl  ] = acc[0];
                stage[cl+1][rl  ] = acc[1];
                stage[cl  ][rl+8] = acc[2];
                stage[cl+1][rl+8] = acc[3];
            }
        }
        __syncthreads();
        #pragma unroll
        for (int t=0; t<32; ++t) {
            int idx = tid + 256*t; int nl = idx & 127, dl = idx >> 7;
            g_outT[p][basep + (size_t)dl*Nn + nl] = stage[dl][nl];
        }
        __syncthreads();
    }
}

// ---------------------------------------------------------------------------
// Kernel 5/6: BatchNorm (unchanged)
// ---------------------------------------------------------------------------
__global__ void __launch_bounds__(256) k_bnstats(
    const float* __restrict__ xr, const float* __restrict__ xi,
    const float* __restrict__ gamma)
{
    const int c = blockIdx.x, p = blockIdx.y;
    const int tid = threadIdx.x;
    const float* x = p ? xi : xr;
    const float* o = g_outT[p];
    const float g = gamma[0];

    float s = 0.f, ss = 0.f;
    for (int b = 0; b < Bb; ++b) {
        const int base = b*Cc*Nn + c*Nn;
        for (int n = tid; n < Nn; n += 256) {
            float z = x[base+n] + g*o[base+n];
            s  += z;
            ss += z*z;
        }
    }
    __shared__ float rs[256], rss[256];
    rs[tid] = s; rss[tid] = ss; __syncthreads();
    #pragma unroll
    for (int st = 128; st > 0; st >>= 1) {
        if (tid < st) { rs[tid] += rs[tid+st]; rss[tid] += rss[tid+st]; }
        __syncthreads();
    }
    if (tid == 0) {
        const float inv_cnt = 1.f / (float)Mtot;
        float mean = rs[0] * inv_cnt;
        float var  = rss[0] * inv_cnt - mean*mean;
        g_mean[p][c] = mean;
        g_rstd[p][c] = rsqrtf(var + EPSf);
    }
}

__global__ void __launch_bounds__(256) k_bnapply(
    const float* __restrict__ xr, const float* __restrict__ xi,
    const float* __restrict__ gamma,
    const float* __restrict__ bnwr, const float* __restrict__ bnbr,
    const float* __restrict__ bnwi, const float* __restrict__ bnbi,
    float* __restrict__ out)
{
    const int idx = blockIdx.x*256 + threadIdx.x;
    const int half = Bb*Cc*Nn;
    const int p = idx / half;
    const int rem = idx - p*half;
    const int c = (rem / Nn) % Cc;

    const float* x = p ? xi : xr;
    const float g = gamma[0];
    const float z = x[rem] + g*g_outT[p][rem];
    const float w = p ? bnwi[c] : bnwr[c];
    const float bia = p ? bnbi[c] : bnbr[c];
    out[idx] = (z - g_mean[p][c]) * g_rstd[p][c] * w + bia;
}

// ---------------------------------------------------------------------------
// Launch
// ---------------------------------------------------------------------------
extern "C" void kernel_launch(void* const* d_in, const int* in_sizes, int n_in,
                              void* d_out, int out_size)
{
    const float* xr   = (const float*)d_in[0];
    const float* xi   = (const float*)d_in[1];
    const float* q_wr = (const float*)d_in[2];
    const float* q_wi = (const float*)d_in[3];
    const float* q_br = (const float*)d_in[4];
    const float* q_bi = (const float*)d_in[5];
    const float* k_wr = (const float*)d_in[6];
    const float* k_wi = (const float*)d_in[7];
    const float* k_br = (const float*)d_in[8];
    const float* k_bi = (const float*)d_in[9];
    const float* v_wr = (const float*)d_in[10];
    const float* v_wi = (const float*)d_in[11];
    const float* v_br = (const float*)d_in[12];
    const float* v_bi = (const float*)d_in[13];
    const float* gamma= (const float*)d_in[14];
    const float* bnwr = (const float*)d_in[15];
    const float* bnbr = (const float*)d_in[16];
    const float* bnwi = (const float*)d_in[17];
    const float* bnbi = (const float*)d_in[18];
    float* out = (float*)d_out;

    k_proj<0><<<dim3(Mtot/128, Cc/64), 256>>>(xr, xi, q_wr, q_wi, q_br, q_bi);
    k_proj<1><<<dim3(Mtot/128, Cc/64), 256>>>(xr, xi, k_wr, k_wi, k_br, k_bi);
    k_proj<2><<<dim3(Mtot/128, Cc/64), 256>>>(xr, xi, v_wr, v_wi, v_br, v_bi);

    k_scores<<<dim3(Nn/128, Nn/128, Bb), 256>>>();
    k_softmax<<<Mtot, 256>>>();
    k_av<<<dim3(Nn/128, Cc/64, Bb), 256>>>();

    k_bnstats<<<dim3(Cc, 2), 256>>>(xr, xi, gamma);
    k_bnapply<<<(2*Bb*Cc*Nn)/256, 256>>>(xr, xi, gamma, bnwr, bnbr, bnwi, bnbi, out);
}

// round 3
// speedup vs baseline: 5.1251x; 2.1882x over previous
#include <cuda_runtime.h>
#include <cuda_bf16.h>
#include <math.h>
#include <stdint.h>

#define Bb   8
#define Cc   256
#define Nn   2304
#define Mtot (Bb*Nn)
#define EPSf 1e-5f

// ---------------------------------------------------------------------------
// Scratch
// ---------------------------------------------------------------------------
__device__ __nv_bfloat16 g_q[2][(size_t)Mtot*Cc];
__device__ __nv_bfloat16 g_k[2][(size_t)Mtot*Cc];
__device__ __nv_bfloat16 g_v[2][(size_t)Mtot*Cc];
__device__ float         g_attn [(size_t)Bb*Nn*Nn];
__device__ __nv_bfloat16 g_attnb[(size_t)Bb*Nn*Nn];
__device__ float g_outT[2][(size_t)Bb*Cc*Nn];
__device__ float g_mean[2][Cc];
__device__ float g_rstd[2][Cc];

// ---------------------------------------------------------------------------
// helpers
// ---------------------------------------------------------------------------
__device__ __forceinline__ uint32_t s2u(const void* p){
    return (uint32_t)__cvta_generic_to_shared(p);
}
__device__ __forceinline__ uint32_t packbf(float lo, float hi){
    uint32_t r;
    asm("cvt.rn.bf16x2.f32 %0, %1, %2;" : "=r"(r) : "f"(hi), "f"(lo));
    return r;
}
__device__ __forceinline__ void mma16(float* d, const uint32_t* a, const uint32_t* b){
    asm volatile("mma.sync.aligned.m16n8k16.row.col.f32.bf16.bf16.f32 "
        "{%0,%1,%2,%3}, {%4,%5,%6,%7}, {%8,%9}, {%0,%1,%2,%3};"
        : "+f"(d[0]),"+f"(d[1]),"+f"(d[2]),"+f"(d[3])
        : "r"(a[0]),"r"(a[1]),"r"(a[2]),"r"(a[3]),"r"(b[0]),"r"(b[1]));
}
__device__ __forceinline__ void ldsm4(uint32_t* r, uint32_t addr){
    asm volatile("ldmatrix.sync.aligned.m8n8.x4.shared.b16 {%0,%1,%2,%3}, [%4];"
        : "=r"(r[0]),"=r"(r[1]),"=r"(r[2]),"=r"(r[3]) : "r"(addr));
}
__device__ __forceinline__ void ldsm4t(uint32_t* r, uint32_t addr){
    asm volatile("ldmatrix.sync.aligned.m8n8.x4.trans.shared.b16 {%0,%1,%2,%3}, [%4];"
        : "=r"(r[0]),"=r"(r[1]),"=r"(r[2]),"=r"(r[3]) : "r"(addr));
}
__device__ __forceinline__ void cpa16(uint32_t dst, const void* src){
    asm volatile("cp.async.cg.shared.global [%0], [%1], 16;" :: "r"(dst), "l"(src));
}
#define CP_COMMIT() asm volatile("cp.async.commit_group;")
#define CP_WAIT(N)  asm volatile("cp.async.wait_group %0;" :: "n"(N))

// ---------------------------------------------------------------------------
// Kernel 1: complex projection (fp32 in, bf16 out [m][c])
//   Block 128m x 64d, warps 4(m)x2(d), warp tile 32x32. K-tile 16.
//   X stored [k][m] in smem (natural orientation), A frags via ldmatrix.trans.
// ---------------------------------------------------------------------------
template<int WSEL>
__global__ void __launch_bounds__(256) k_proj(
    const float* __restrict__ xr, const float* __restrict__ xi,
    const float* __restrict__ wr, const float* __restrict__ wi,
    const float* __restrict__ brv, const float* __restrict__ biv)
{
    __nv_bfloat16* yr = (WSEL==0)?g_q[0]:(WSEL==1)?g_k[0]:g_v[0];
    __nv_bfloat16* yi = (WSEL==0)?g_q[1]:(WSEL==1)?g_k[1]:g_v[1];

    __shared__ __nv_bfloat16 sX[2][16][136];   // [part][k][m]
    __shared__ __nv_bfloat16 sW[2][64][24];    // [part][d][k]

    const int tid = threadIdx.x;
    const int w = tid >> 5, lane = tid & 31;
    const int gr = lane >> 2, tg = lane & 3;
    const int wm = w & 3, wn = w >> 2;
    const int m0 = blockIdx.x * 128;
    const int d0 = blockIdx.y * 64;
    const int b  = m0 / Nn;
    const int n0 = m0 - b*Nn;

    const int lp = tid >> 7;        // load part (0/1), 128 threads each
    const int lt = tid & 127;

    float accr[2][4][4], acci[2][4][4];
    #pragma unroll
    for (int mf=0; mf<2; ++mf)
        #pragma unroll
        for (int nf=0; nf<4; ++nf)
            #pragma unroll
            for (int e=0; e<4; ++e){ accr[mf][nf][e]=0.f; acci[mf][nf][e]=0.f; }

    for (int kt = 0; kt < Cc/16; ++kt) {
        const int ck = kt*16;
        const float* xs = lp ? xi : xr;
        const float* ws = lp ? wi : wr;
        #pragma unroll
        for (int it=0; it<4; ++it) {         // X: [c][n] gmem, 4 floats along n
            int idx = lt + 128*it;
            int c = idx >> 5, nq = idx & 31;
            const float4 v = *(const float4*)(xs + (size_t)b*Cc*Nn + (size_t)(ck+c)*Nn + n0 + nq*4);
            uint2 pk = make_uint2(packbf(v.x,v.y), packbf(v.z,v.w));
            *(uint2*)&sX[lp][c][nq*4] = pk;
        }
        #pragma unroll
        for (int it=0; it<2; ++it) {         // W: [d][c] gmem, 4 floats along c
            int idx = lt + 128*it;
            int d = idx >> 2, cq = idx & 3;
            const float4 v = *(const float4*)(ws + (size_t)(d0+d)*Cc + ck + cq*4);
            uint2 pk = make_uint2(packbf(v.x,v.y), packbf(v.z,v.w));
            *(uint2*)&sW[lp][d][cq*4] = pk;
        }
        __syncthreads();

        uint32_t axr[2][4], axi[2][4], ain[2][4];
        #pragma unroll
        for (int mf=0; mf<2; ++mf) {
            int rb = wm*32 + mf*16;
            uint32_t ax = s2u(&sX[0][(lane&7) + (lane>>4)*8][rb + ((lane>>3)&1)*8]);
            uint32_t ay = s2u(&sX[1][(lane&7) + (lane>>4)*8][rb + ((lane>>3)&1)*8]);
            ldsm4t(axr[mf], ax);
            ldsm4t(axi[mf], ay);
            #pragma unroll
            for (int e=0;e<4;++e) ain[mf][e] = axi[mf][e] ^ 0x80008000u;
        }
        #pragma unroll
        for (int nf2=0; nf2<2; ++nf2) {
            int cb = wn*32 + nf2*16;
            uint32_t bwr[4], bwi[4];
            uint32_t br_ = s2u(&sW[0][cb + (lane>>4)*8 + (lane&7)][((lane>>3)&1)*8]);
            uint32_t bi_ = s2u(&sW[1][cb + (lane>>4)*8 + (lane&7)][((lane>>3)&1)*8]);
            ldsm4(bwr, br_);
            ldsm4(bwi, bi_);
            #pragma unroll
            for (int h=0; h<2; ++h) {
                int nfr = nf2*2 + h;
                #pragma unroll
                for (int mf=0; mf<2; ++mf) {
                    mma16(accr[mf][nfr], axr[mf], bwr + 2*h);   //  Xr*Wr
                    mma16(accr[mf][nfr], ain[mf], bwi + 2*h);   // -Xi*Wi
                    mma16(acci[mf][nfr], axr[mf], bwi + 2*h);   //  Xr*Wi
                    mma16(acci[mf][nfr], axi[mf], bwr + 2*h);   //  Xi*Wr
                }
            }
        }
        __syncthreads();
    }

    #pragma unroll
    for (int mf=0; mf<2; ++mf) {
        const int row0 = m0 + wm*32 + mf*16 + gr;
        #pragma unroll
        for (int nfr=0; nfr<4; ++nfr) {
            const int col0 = d0 + wn*32 + nfr*8 + 2*tg;
            const float b0r = brv[col0], b1r = brv[col0+1];
            const float b0i = biv[col0], b1i = biv[col0+1];
            *(uint32_t*)&yr[(size_t)row0*Cc + col0]     = packbf(accr[mf][nfr][0]+b0r, accr[mf][nfr][1]+b1r);
            *(uint32_t*)&yr[(size_t)(row0+8)*Cc + col0] = packbf(accr[mf][nfr][2]+b0r, accr[mf][nfr][3]+b1r);
            *(uint32_t*)&yi[(size_t)row0*Cc + col0]     = packbf(acci[mf][nfr][0]+b0i, acci[mf][nfr][1]+b1i);
            *(uint32_t*)&yi[(size_t)(row0+8)*Cc + col0] = packbf(acci[mf][nfr][2]+b0i, acci[mf][nfr][3]+b1i);
        }
    }
}

// ---------------------------------------------------------------------------
// Kernel 2: scores  S = (Qr Kr^T + Qi Ki^T)/16
//   Block 128n x 128m, warps 2(n)x4(m), warp tile 64x32.
//   bf16 cp.async double-buffered, ldmatrix fragments.
// ---------------------------------------------------------------------------
__global__ void __launch_bounds__(256) k_scores()
{
    __shared__ __nv_bfloat16 sQ[2][2][128][24];   // [stage][part][row][k]
    __shared__ __nv_bfloat16 sK[2][2][128][24];

    const int tid = threadIdx.x;
    const int w = tid >> 5, lane = tid & 31;
    const int gr = lane >> 2, tg = lane & 3;
    const int wrow = w & 1, wcol = w >> 1;
    const int m0 = blockIdx.x * 128;
    const int n0 = blockIdx.y * 128;
    const int b  = blockIdx.z;

    const __nv_bfloat16* qp0 = g_q[0] + (size_t)b*Nn*Cc;
    const __nv_bfloat16* qp1 = g_q[1] + (size_t)b*Nn*Cc;
    const __nv_bfloat16* kp0 = g_k[0] + (size_t)b*Nn*Cc;
    const __nv_bfloat16* kp1 = g_k[1] + (size_t)b*Nn*Cc;

    const int lrow = tid >> 1, lhalf = tid & 1;

    float acc[4][4][4];
    #pragma unroll
    for (int mf=0; mf<4; ++mf)
        #pragma unroll
        for (int nf=0; nf<4; ++nf)
            #pragma unroll
            for (int e=0; e<4; ++e) acc[mf][nf][e]=0.f;

    // prologue load stage 0, ck=0
    {
        cpa16(s2u(&sQ[0][0][lrow][lhalf*8]), qp0 + (size_t)(n0+lrow)*Cc + lhalf*8);
        cpa16(s2u(&sQ[0][1][lrow][lhalf*8]), qp1 + (size_t)(n0+lrow)*Cc + lhalf*8);
        cpa16(s2u(&sK[0][0][lrow][lhalf*8]), kp0 + (size_t)(m0+lrow)*Cc + lhalf*8);
        cpa16(s2u(&sK[0][1][lrow][lhalf*8]), kp1 + (size_t)(m0+lrow)*Cc + lhalf*8);
        CP_COMMIT();
    }

    for (int kt = 0; kt < 16; ++kt) {
        if (kt < 15) {
            const int ck = (kt+1)*16;
            const int s = (kt+1)&1;
            cpa16(s2u(&sQ[s][0][lrow][lhalf*8]), qp0 + (size_t)(n0+lrow)*Cc + ck + lhalf*8);
            cpa16(s2u(&sQ[s][1][lrow][lhalf*8]), qp1 + (size_t)(n0+lrow)*Cc + ck + lhalf*8);
            cpa16(s2u(&sK[s][0][lrow][lhalf*8]), kp0 + (size_t)(m0+lrow)*Cc + ck + lhalf*8);
            cpa16(s2u(&sK[s][1][lrow][lhalf*8]), kp1 + (size_t)(m0+lrow)*Cc + ck + lhalf*8);
            CP_COMMIT();
            CP_WAIT(1);
        } else {
            CP_WAIT(0);
        }
        __syncthreads();
        const int s = kt&1;
        #pragma unroll
        for (int p=0; p<2; ++p) {
            uint32_t a[4][4];
            #pragma unroll
            for (int mf=0; mf<4; ++mf) {
                int rb = wrow*64 + mf*16;
                ldsm4(a[mf], s2u(&sQ[s][p][rb + (lane&15)][(lane>>4)*8]));
            }
            #pragma unroll
            for (int nf2=0; nf2<2; ++nf2) {
                int cb = wcol*32 + nf2*16;
                uint32_t bb[4];
                ldsm4(bb, s2u(&sK[s][p][cb + (lane>>4)*8 + (lane&7)][((lane>>3)&1)*8]));
                #pragma unroll
                for (int mf=0; mf<4; ++mf) {
                    mma16(acc[mf][nf2*2  ], a[mf], bb);
                    mma16(acc[mf][nf2*2+1], a[mf], bb+2);
                }
            }
        }
        __syncthreads();
    }

    const float sc = 1.0f/16.0f;
    #pragma unroll
    for (int mf=0; mf<4; ++mf) {
        const int row0 = n0 + wrow*64 + mf*16 + gr;
        const size_t r0b = (size_t)b*Nn*Nn + (size_t)row0*Nn;
        const size_t r1b = r0b + (size_t)8*Nn;
        #pragma unroll
        for (int nfr=0; nfr<4; ++nfr) {
            const int col0 = m0 + wcol*32 + nfr*8 + 2*tg;
            g_attn[r0b + col0  ] = acc[mf][nfr][0]*sc;
            g_attn[r0b + col0+1] = acc[mf][nfr][1]*sc;
            g_attn[r1b + col0  ] = acc[mf][nfr][2]*sc;
            g_attn[r1b + col0+1] = acc[mf][nfr][3]*sc;
        }
    }
}

// ---------------------------------------------------------------------------
// Kernel 3: softmax — fp32 logits in, bf16 probabilities out
// ---------------------------------------------------------------------------
__global__ void __launch_bounds__(256) k_softmax()
{
    const size_t base = (size_t)blockIdx.x * Nn;
    const int tid = threadIdx.x;
    __shared__ float red[256];

    float v[9];
    float mx = -1e30f;
    #pragma unroll
    for (int i = 0; i < 9; ++i) { v[i] = g_attn[base + tid + 256*i]; mx = fmaxf(mx, v[i]); }

    red[tid] = mx; __syncthreads();
    #pragma unroll
    for (int s = 128; s > 0; s >>= 1) {
        if (tid < s) red[tid] = fmaxf(red[tid], red[tid+s]);
        __syncthreads();
    }
    mx = red[0]; __syncthreads();

    float sum = 0.f;
    #pragma unroll
    for (int i = 0; i < 9; ++i) { v[i] = __expf(v[i] - mx); sum += v[i]; }

    red[tid] = sum; __syncthreads();
    #pragma unroll
    for (int s = 128; s > 0; s >>= 1) {
        if (tid < s) red[tid] += red[tid+s];
        __syncthreads();
    }
    const float inv = 1.f / red[0];
    #pragma unroll
    for (int i = 0; i < 9; ++i)
        g_attnb[base + tid + 256*i] = __float2bfloat16(v[i] * inv);
}

// ---------------------------------------------------------------------------
// Kernel 4: AV  (A bf16 [n][m]) x (V bf16 [m][d]) -> g_outT fp32 [d][n]
//   Block 128n x 64d, warps 4(n)x2(d), warp 32x32. k over m, double-buffered.
// ---------------------------------------------------------------------------
__global__ void __launch_bounds__(256) k_av()
{
    __shared__ __align__(16) unsigned char raw[64*129*4];   // 33024 B union
    __nv_bfloat16 (*sA)[128][24]   = (__nv_bfloat16(*)[128][24])raw;          // 2 stages, 12288 B
    __nv_bfloat16 (*sV)[2][16][72] = (__nv_bfloat16(*)[2][16][72])(raw+12288);// 2 stages, 9216 B
    float (*stage)[129] = (float(*)[129])raw;

    const int tid = threadIdx.x;
    const int w = tid >> 5, lane = tid & 31;
    const int gr = lane >> 2, tg = lane & 3;
    const int wm = w & 3, wn = w >> 2;
    const int n0 = blockIdx.x * 128;
    const int d0 = blockIdx.y * 64;
    const int b  = blockIdx.z;

    const __nv_bfloat16* Ab = g_attnb + (size_t)b*Nn*Nn;
    const __nv_bfloat16* vp0 = g_v[0] + (size_t)b*Nn*Cc;
    const __nv_bfloat16* vp1 = g_v[1] + (size_t)b*Nn*Cc;

    const int rowA = tid >> 1, halfA = tid & 1;
    const int pV = (tid >> 7) & 1, rowV = (tid >> 3) & 15, chV = tid & 7;
    const __nv_bfloat16* vsrc = pV ? vp1 : vp0;

    float accr[2][4][4], acci[2][4][4];
    #pragma unroll
    for (int mf=0; mf<2; ++mf)
        #pragma unroll
        for (int nf=0; nf<4; ++nf)
            #pragma unroll
            for (int e=0; e<4; ++e){ accr[mf][nf][e]=0.f; acci[mf][nf][e]=0.f; }

    {
        cpa16(s2u(&sA[0][rowA][halfA*8]), Ab + (size_t)(n0+rowA)*Nn + halfA*8);
        cpa16(s2u(&sV[0][pV][rowV][chV*8]), vsrc + (size_t)rowV*Cc + d0 + chV*8);
        CP_COMMIT();
    }

    for (int kt = 0; kt < Nn/16; ++kt) {
        if (kt < Nn/16 - 1) {
            const int mk = (kt+1)*16;
            const int s = (kt+1)&1;
            cpa16(s2u(&sA[s][rowA][halfA*8]), Ab + (size_t)(n0+rowA)*Nn + mk + halfA*8);
            cpa16(s2u(&sV[s][pV][rowV][chV*8]), vsrc + (size_t)(mk+rowV)*Cc + d0 + chV*8);
            CP_COMMIT();
            CP_WAIT(1);
        } else {
            CP_WAIT(0);
        }
        __syncthreads();
        const int s = kt&1;

        uint32_t a[2][4];
        #pragma unroll
        for (int mf=0; mf<2; ++mf) {
            int rb = wm*32 + mf*16;
            ldsm4(a[mf], s2u(&sA[s][rb + (lane&15)][(lane>>4)*8]));
        }
        #pragma unroll
        for (int nf2=0; nf2<2; ++nf2) {
            int cb = wn*32 + nf2*16;
            uint32_t bvr[4], bvi[4];
            ldsm4t(bvr, s2u(&sV[s][0][lane&15][cb + (lane>>4)*8]));
            ldsm4t(bvi, s2u(&sV[s][1][lane&15][cb + (lane>>4)*8]));
            #pragma unroll
            for (int h=0; h<2; ++h) {
                int nfr = nf2*2 + h;
                #pragma unroll
                for (int mf=0; mf<2; ++mf) {
                    mma16(accr[mf][nfr], a[mf], bvr + 2*h);
                    mma16(acci[mf][nfr], a[mf], bvi + 2*h);
                }
            }
        }
        __syncthreads();
    }

    // transpose epilogue -> g_outT [d][n] fp32
    const size_t basep = (size_t)b*Cc*Nn + (size_t)d0*Nn + n0;
    #pragma unroll
    for (int p=0; p<2; ++p) {
        #pragma unroll
        for (int mf=0; mf<2; ++mf) {
            int rl = wm*32 + mf*16 + gr;
            #pragma unroll
            for (int nfr=0; nfr<4; ++nfr) {
                int cl = wn*32 + nfr*8 + 2*tg;
                float* acc = p ? acci[mf][nfr] : accr[mf][nfr];
                stage[cl  ][rl  ] = acc[0];
                stage[cl+1][rl  ] = acc[1];
                stage[cl  ][rl+8] = acc[2];
                stage[cl+1][rl+8] = acc[3];
            }
        }
        __syncthreads();
        #pragma unroll
        for (int t=0; t<32; ++t) {
            int idx = tid + 256*t; int nl = idx & 127, dl = idx >> 7;
            g_outT[p][basep + (size_t)dl*Nn + nl] = stage[dl][nl];
        }
        __syncthreads();
    }
}

// ---------------------------------------------------------------------------
// Kernel 5/6: BatchNorm
// ---------------------------------------------------------------------------
__global__ void __launch_bounds__(256) k_bnstats(
    const float* __restrict__ xr, const float* __restrict__ xi,
    const float* __restrict__ gamma)
{
    const int c = blockIdx.x, p = blockIdx.y;
    const int tid = threadIdx.x;
    const float* x = p ? xi : xr;
    const float* o = g_outT[p];
    const float g = gamma[0];

    float s = 0.f, ss = 0.f;
    for (int b = 0; b < Bb; ++b) {
        const int base = b*Cc*Nn + c*Nn;
        for (int n = tid; n < Nn; n += 256) {
            float z = x[base+n] + g*o[base+n];
            s  += z;
            ss += z*z;
        }
    }
    __shared__ float rs[256], rss[256];
    rs[tid] = s; rss[tid] = ss; __syncthreads();
    #pragma unroll
    for (int st = 128; st > 0; st >>= 1) {
        if (tid < st) { rs[tid] += rs[tid+st]; rss[tid] += rss[tid+st]; }
        __syncthreads();
    }
    if (tid == 0) {
        const float inv_cnt = 1.f / (float)Mtot;
        float mean = rs[0] * inv_cnt;
        float var  = rss[0] * inv_cnt - mean*mean;
        g_mean[p][c] = mean;
        g_rstd[p][c] = rsqrtf(var + EPSf);
    }
}

__global__ void __launch_bounds__(256) k_bnapply(
    const float* __restrict__ xr, const float* __restrict__ xi,
    const float* __restrict__ gamma,
    const float* __restrict__ bnwr, const float* __restrict__ bnbr,
    const float* __restrict__ bnwi, const float* __restrict__ bnbi,
    float* __restrict__ out)
{
    const int idx = blockIdx.x*256 + threadIdx.x;
    const int half = Bb*Cc*Nn;
    const int p = idx / half;
    const int rem = idx - p*half;
    const int c = (rem / Nn) % Cc;

    const float* x = p ? xi : xr;
    const float g = gamma[0];
    const float z = x[rem] + g*g_outT[p][rem];
    const float w = p ? bnwi[c] : bnwr[c];
    const float bia = p ? bnbi[c] : bnbr[c];
    out[idx] = (z - g_mean[p][c]) * g_rstd[p][c] * w + bia;
}

// ---------------------------------------------------------------------------
// Launch
// ---------------------------------------------------------------------------
extern "C" void kernel_launch(void* const* d_in, const int* in_sizes, int n_in,
                              void* d_out, int out_size)
{
    const float* xr   = (const float*)d_in[0];
    const float* xi   = (const float*)d_in[1];
    const float* q_wr = (const float*)d_in[2];
    const float* q_wi = (const float*)d_in[3];
    const float* q_br = (const float*)d_in[4];
    const float* q_bi = (const float*)d_in[5];
    const float* k_wr = (const float*)d_in[6];
    const float* k_wi = (const float*)d_in[7];
    const float* k_br = (const float*)d_in[8];
    const float* k_bi = (const float*)d_in[9];
    const float* v_wr = (const float*)d_in[10];
    const float* v_wi = (const float*)d_in[11];
    const float* v_br = (const float*)d_in[12];
    const float* v_bi = (const float*)d_in[13];
    const float* gamma= (const float*)d_in[14];
    const float* bnwr = (const float*)d_in[15];
    const float* bnbr = (const float*)d_in[16];
    const float* bnwi = (const float*)d_in[17];
    const float* bnbi = (const float*)d_in[18];
    float* out = (float*)d_out;

    k_proj<0><<<dim3(Mtot/128, Cc/64), 256>>>(xr, xi, q_wr, q_wi, q_br, q_bi);
    k_proj<1><<<dim3(Mtot/128, Cc/64), 256>>>(xr, xi, k_wr, k_wi, k_br, k_bi);
    k_proj<2><<<dim3(Mtot/128, Cc/64), 256>>>(xr, xi, v_wr, v_wi, v_br, v_bi);

    k_scores<<<dim3(Nn/128, Nn/128, Bb), 256>>>();
    k_softmax<<<Mtot, 256>>>();
    k_av<<<dim3(Nn/128, Cc/64, Bb), 256>>>();

    k_bnstats<<<dim3(Cc, 2), 256>>>(xr, xi, gamma);
    k_bnapply<<<(2*Bb*Cc*Nn)/256, 256>>>(xr, xi, gamma, bnwr, bnbr, bnwi, bnbi, out);
}

// round 5
// speedup vs baseline: 6.7019x; 1.3077x over previous
#include <cuda_runtime.h>
#include <cuda_bf16.h>
#include <math.h>
#include <stdint.h>

#define Bb   8
#define Cc   256
#define Nn   2304
#define Mtot (Bb*Nn)
#define EPSf 1e-5f

// ---------------------------------------------------------------------------
// Scratch
// ---------------------------------------------------------------------------
__device__ __align__(128) __nv_bfloat16 g_q[2][(size_t)Mtot*Cc];
__device__ __align__(128) __nv_bfloat16 g_k[2][(size_t)Mtot*Cc];
__device__ __align__(128) __nv_bfloat16 g_v[2][(size_t)Mtot*Cc];
__device__ __align__(128) float         g_attn [(size_t)Bb*Nn*Nn];
__device__ __align__(128) __nv_bfloat16 g_attnb[(size_t)Bb*Nn*Nn];
__device__ __align__(128) float g_outT[2][(size_t)Bb*Cc*Nn];
__device__ float g_mean[2][Cc];
__device__ float g_rstd[2][Cc];

// ---------------------------------------------------------------------------
// helpers
// ---------------------------------------------------------------------------
__device__ __forceinline__ uint32_t s2u(const void* p){
    return (uint32_t)__cvta_generic_to_shared(p);
}
__device__ __forceinline__ uint32_t packbf(float lo, float hi){
    uint32_t r;
    asm("cvt.rn.bf16x2.f32 %0, %1, %2;" : "=r"(r) : "f"(hi), "f"(lo));
    return r;
}
__device__ __forceinline__ void mma16(float* d, const uint32_t* a, const uint32_t* b){
    asm volatile("mma.sync.aligned.m16n8k16.row.col.f32.bf16.bf16.f32 "
        "{%0,%1,%2,%3}, {%4,%5,%6,%7}, {%8,%9}, {%0,%1,%2,%3};"
        : "+f"(d[0]),"+f"(d[1]),"+f"(d[2]),"+f"(d[3])
        : "r"(a[0]),"r"(a[1]),"r"(a[2]),"r"(a[3]),"r"(b[0]),"r"(b[1]));
}
__device__ __forceinline__ void ldsm4(uint32_t* r, uint32_t addr){
    asm volatile("ldmatrix.sync.aligned.m8n8.x4.shared.b16 {%0,%1,%2,%3}, [%4];"
        : "=r"(r[0]),"=r"(r[1]),"=r"(r[2]),"=r"(r[3]) : "r"(addr));
}
__device__ __forceinline__ void ldsm4t(uint32_t* r, uint32_t addr){
    asm volatile("ldmatrix.sync.aligned.m8n8.x4.trans.shared.b16 {%0,%1,%2,%3}, [%4];"
        : "=r"(r[0]),"=r"(r[1]),"=r"(r[2]),"=r"(r[3]) : "r"(addr));
}
__device__ __forceinline__ void cpa16(uint32_t dst, const void* src){
    asm volatile("cp.async.cg.shared.global [%0], [%1], 16;" :: "r"(dst), "l"(src));
}
#define CP_COMMIT() asm volatile("cp.async.commit_group;")
#define CP_WAIT(N)  asm volatile("cp.async.wait_group %0;" :: "n"(N))

// 64B-row smem tile: swizzled 16B-chunk offset (conflict-free for ldsm + cp.async)
__device__ __forceinline__ uint32_t sw64(uint32_t tile, int r, int c16){
    return tile + (uint32_t)r*64u + (uint32_t)((c16 ^ ((r>>1)&3))<<4);
}

// ---------------------------------------------------------------------------
// Kernel 1: complex projection (mma.sync bf16), fp32 in, bf16 out [m][c]
// ---------------------------------------------------------------------------
template<int WSEL>
__global__ void __launch_bounds__(256) k_proj(
    const float* __restrict__ xr, const float* __restrict__ xi,
    const float* __restrict__ wr, const float* __restrict__ wi,
    const float* __restrict__ brv, const float* __restrict__ biv)
{
    __nv_bfloat16* yr = (WSEL==0)?g_q[0]:(WSEL==1)?g_k[0]:g_v[0];
    __nv_bfloat16* yi = (WSEL==0)?g_q[1]:(WSEL==1)?g_k[1]:g_v[1];

    __shared__ __nv_bfloat16 sX[2][16][136];   // [part][k][m]
    __shared__ __nv_bfloat16 sW[2][64][24];    // [part][d][k]

    const int tid = threadIdx.x;
    const int w = tid >> 5, lane = tid & 31;
    const int gr = lane >> 2, tg = lane & 3;
    const int wm = w & 3, wn = w >> 2;
    const int m0 = blockIdx.x * 128;
    const int d0 = blockIdx.y * 64;
    const int b  = m0 / Nn;
    const int n0 = m0 - b*Nn;

    const int lp = tid >> 7;
    const int lt = tid & 127;

    float accr[2][4][4], acci[2][4][4];
    #pragma unroll
    for (int mf=0; mf<2; ++mf)
        #pragma unroll
        for (int nf=0; nf<4; ++nf)
            #pragma unroll
            for (int e=0; e<4; ++e){ accr[mf][nf][e]=0.f; acci[mf][nf][e]=0.f; }

    for (int kt = 0; kt < Cc/16; ++kt) {
        const int ck = kt*16;
        const float* xs = lp ? xi : xr;
        const float* ws = lp ? wi : wr;
        #pragma unroll
        for (int it=0; it<4; ++it) {
            int idx = lt + 128*it;
            int c = idx >> 5, nq = idx & 31;
            const float4 v = *(const float4*)(xs + (size_t)b*Cc*Nn + (size_t)(ck+c)*Nn + n0 + nq*4);
            uint2 pk = make_uint2(packbf(v.x,v.y), packbf(v.z,v.w));
            *(uint2*)&sX[lp][c][nq*4] = pk;
        }
        #pragma unroll
        for (int it=0; it<2; ++it) {
            int idx = lt + 128*it;
            int d = idx >> 2, cq = idx & 3;
            const float4 v = *(const float4*)(ws + (size_t)(d0+d)*Cc + ck + cq*4);
            uint2 pk = make_uint2(packbf(v.x,v.y), packbf(v.z,v.w));
            *(uint2*)&sW[lp][d][cq*4] = pk;
        }
        __syncthreads();

        uint32_t axr[2][4], axi[2][4], ain[2][4];
        #pragma unroll
        for (int mf=0; mf<2; ++mf) {
            int rb = wm*32 + mf*16;
            ldsm4t(axr[mf], s2u(&sX[0][(lane&7) + (lane>>4)*8][rb + ((lane>>3)&1)*8]));
            ldsm4t(axi[mf], s2u(&sX[1][(lane&7) + (lane>>4)*8][rb + ((lane>>3)&1)*8]));
            #pragma unroll
            for (int e=0;e<4;++e) ain[mf][e] = axi[mf][e] ^ 0x80008000u;
        }
        #pragma unroll
        for (int nf2=0; nf2<2; ++nf2) {
            int cb = wn*32 + nf2*16;
            uint32_t bwr[4], bwi[4];
            ldsm4(bwr, s2u(&sW[0][cb + (lane>>4)*8 + (lane&7)][((lane>>3)&1)*8]));
            ldsm4(bwi, s2u(&sW[1][cb + (lane>>4)*8 + (lane&7)][((lane>>3)&1)*8]));
            #pragma unroll
            for (int h=0; h<2; ++h) {
                int nfr = nf2*2 + h;
                #pragma unroll
                for (int mf=0; mf<2; ++mf) {
                    mma16(accr[mf][nfr], axr[mf], bwr + 2*h);
                    mma16(accr[mf][nfr], ain[mf], bwi + 2*h);
                    mma16(acci[mf][nfr], axr[mf], bwi + 2*h);
                    mma16(acci[mf][nfr], axi[mf], bwr + 2*h);
                }
            }
        }
        __syncthreads();
    }

    #pragma unroll
    for (int mf=0; mf<2; ++mf) {
        const int row0 = m0 + wm*32 + mf*16 + gr;
        #pragma unroll
        for (int nfr=0; nfr<4; ++nfr) {
            const int col0 = d0 + wn*32 + nfr*8 + 2*tg;
            const float b0r = brv[col0], b1r = brv[col0+1];
            const float b0i = biv[col0], b1i = biv[col0+1];
            *(uint32_t*)&yr[(size_t)row0*Cc + col0]     = packbf(accr[mf][nfr][0]+b0r, accr[mf][nfr][1]+b1r);
            *(uint32_t*)&yr[(size_t)(row0+8)*Cc + col0] = packbf(accr[mf][nfr][2]+b0r, accr[mf][nfr][3]+b1r);
            *(uint32_t*)&yi[(size_t)row0*Cc + col0]     = packbf(acci[mf][nfr][0]+b0i, acci[mf][nfr][1]+b1i);
            *(uint32_t*)&yi[(size_t)(row0+8)*Cc + col0] = packbf(acci[mf][nfr][2]+b0i, acci[mf][nfr][3]+b1i);
        }
    }
}

// ---------------------------------------------------------------------------
// Kernel 2: scores. Block 128n x 128m, warps 2(n)x4(m), warp 64x32.
//   3-stage cp.async ring, K-step 32 per stage (both parts), swizzled smem.
//   Stage layout: [Q0 | Q1 | K0 | K1], each tile 128 rows x 64B = 8192B.
// ---------------------------------------------------------------------------
#define SC_STAGE 32768
#define SC_SMEM  (3*SC_STAGE)

__global__ void __launch_bounds__(256) k_scores()
{
    extern __shared__ __align__(16) unsigned char dyn[];
    const uint32_t base = s2u(dyn);

    const int tid = threadIdx.x;
    const int w = tid >> 5, lane = tid & 31;
    const int gr = lane >> 2, tg = lane & 3;
    const int wrow = w & 1, wcol = w >> 1;
    const int m0 = blockIdx.x * 128;
    const int n0 = blockIdx.y * 128;
    const int b  = blockIdx.z;

    const __nv_bfloat16* srcs[4] = {
        g_q[0] + (size_t)b*Nn*Cc, g_q[1] + (size_t)b*Nn*Cc,
        g_k[0] + (size_t)b*Nn*Cc, g_k[1] + (size_t)b*Nn*Cc };
    const int rbase[4] = { n0, n0, m0, m0 };

    float acc[4][4][4];
    #pragma unroll
    for (int mf=0; mf<4; ++mf)
        #pragma unroll
        for (int nf=0; nf<4; ++nf)
            #pragma unroll
            for (int e=0; e<4; ++e) acc[mf][nf][e]=0.f;

    // stage loader
    auto load_stage = [&](int s, int ck){
        const uint32_t st = base + s*SC_STAGE;
        #pragma unroll
        for (int t=0;t<4;++t){
            const uint32_t tb = st + t*8192;
            #pragma unroll
            for (int it=0; it<2; ++it){
                int idx = tid + 256*it;
                int r = idx>>2, c = idx&3;
                cpa16(sw64(tb, r, c), srcs[t] + (size_t)(rbase[t]+r)*Cc + ck + c*8);
            }
        }
        CP_COMMIT();
    };

    load_stage(0, 0);
    load_stage(1, 32);
    CP_WAIT(1);
    __syncthreads();

    for (int kt = 0; kt < 8; ++kt) {
        const int s = kt % 3;
        if (kt + 2 < 8) load_stage((kt+2)%3, (kt+2)*32);

        const uint32_t st = base + s*SC_STAGE;
        #pragma unroll
        for (int p=0; p<2; ++p) {
            const uint32_t qt = st + p*8192;
            const uint32_t ktile = st + 16384 + p*8192;
            #pragma unroll
            for (int ks=0; ks<32; ks+=16) {
                uint32_t a[4][4];
                #pragma unroll
                for (int mf=0; mf<4; ++mf) {
                    int r = wrow*64 + mf*16 + (lane&15);
                    int c16 = (ks>>3) + (lane>>4);
                    ldsm4(a[mf], sw64(qt, r, c16));
                }
                #pragma unroll
                for (int nf2=0; nf2<2; ++nf2) {
                    int rr = wcol*32 + nf2*16 + (lane>>4)*8 + (lane&7);
                    int c16 = (ks>>3) + ((lane>>3)&1);
                    uint32_t bb[4];
                    ldsm4(bb, sw64(ktile, rr, c16));
                    #pragma unroll
                    for (int mf=0; mf<4; ++mf) {
                        mma16(acc[mf][nf2*2  ], a[mf], bb);
                        mma16(acc[mf][nf2*2+1], a[mf], bb+2);
                    }
                }
            }
        }
        if (kt + 2 < 8) { CP_WAIT(1); } else if (kt + 1 < 8) { CP_WAIT(0); }
        __syncthreads();
    }

    const float sc = 1.0f/16.0f;
    #pragma unroll
    for (int mf=0; mf<4; ++mf) {
        const int row0 = n0 + wrow*64 + mf*16 + gr;
        const size_t r0b = (size_t)b*Nn*Nn + (size_t)row0*Nn;
        const size_t r1b = r0b + (size_t)8*Nn;
        #pragma unroll
        for (int nfr=0; nfr<4; ++nfr) {
            const int col0 = m0 + wcol*32 + nfr*8 + 2*tg;
            g_attn[r0b + col0  ] = acc[mf][nfr][0]*sc;
            g_attn[r0b + col0+1] = acc[mf][nfr][1]*sc;
            g_attn[r1b + col0  ] = acc[mf][nfr][2]*sc;
            g_attn[r1b + col0+1] = acc[mf][nfr][3]*sc;
        }
    }
}

// ---------------------------------------------------------------------------
// Kernel 3: softmax — fp32 in g_attn, bf16 out g_attnb
// ---------------------------------------------------------------------------
__global__ void __launch_bounds__(256) k_softmax()
{
    const size_t bb = (size_t)blockIdx.x * Nn;
    const int tid = threadIdx.x;
    __shared__ float red[256];

    float v[9];
    float mx = -1e30f;
    #pragma unroll
    for (int i = 0; i < 9; ++i) { v[i] = g_attn[bb + tid + 256*i]; mx = fmaxf(mx, v[i]); }

    red[tid] = mx; __syncthreads();
    #pragma unroll
    for (int s = 128; s > 0; s >>= 1) {
        if (tid < s) red[tid] = fmaxf(red[tid], red[tid+s]);
        __syncthreads();
    }
    mx = red[0]; __syncthreads();

    float sum = 0.f;
    #pragma unroll
    for (int i = 0; i < 9; ++i) { v[i] = __expf(v[i] - mx); sum += v[i]; }

    red[tid] = sum; __syncthreads();
    #pragma unroll
    for (int s = 128; s > 0; s >>= 1) {
        if (tid < s) red[tid] += red[tid+s];
        __syncthreads();
    }
    const float inv = 1.f / red[0];
    #pragma unroll
    for (int i = 0; i < 9; ++i)
        g_attnb[bb + tid + 256*i] = __float2bfloat16(v[i] * inv);
}

// ---------------------------------------------------------------------------
// Kernel 4: AV. Block 128n x 64d, warps 4(n)x2(d), warp 32x32.
//   3-stage ring, K-step 32 over m. Stage: A (128x64B swz, 8192B) +
//   V [2 parts][32 rows][72 cols] (9216B) = 17408B.
// ---------------------------------------------------------------------------
#define AV_STAGE 17408
#define AV_SMEM  (3*AV_STAGE)

__global__ void __launch_bounds__(256) k_av()
{
    extern __shared__ __align__(16) unsigned char dyn[];
    const uint32_t base = s2u(dyn);

    const int tid = threadIdx.x;
    const int w = tid >> 5, lane = tid & 31;
    const int gr = lane >> 2, tg = lane & 3;
    const int wm = w & 3, wn = w >> 2;
    const int n0 = blockIdx.x * 128;
    const int d0 = blockIdx.y * 64;
    const int b  = blockIdx.z;

    const __nv_bfloat16* Ab  = g_attnb + (size_t)b*Nn*Nn;
    const __nv_bfloat16* vp[2] = { g_v[0] + (size_t)b*Nn*Cc, g_v[1] + (size_t)b*Nn*Cc };

    float accr[2][4][4], acci[2][4][4];
    #pragma unroll
    for (int mf=0; mf<2; ++mf)
        #pragma unroll
        for (int nf=0; nf<4; ++nf)
            #pragma unroll
            for (int e=0; e<4; ++e){ accr[mf][nf][e]=0.f; acci[mf][nf][e]=0.f; }

    auto load_stage = [&](int s, int mk){
        const uint32_t st = base + s*AV_STAGE;
        // A: 128 rows x 4 chunks (swizzled 64B rows)
        #pragma unroll
        for (int it=0; it<2; ++it){
            int idx = tid + 256*it;
            int r = idx>>2, c = idx&3;
            cpa16(sw64(st, r, c), Ab + (size_t)(n0+r)*Nn + mk + c*8);
        }
        // V: 2 parts x 32 rows x 8 chunks, padded rows of 72 elems (144B)
        #pragma unroll
        for (int it=0; it<2; ++it){
            int idx = tid + 256*it;
            int p = idx>>8, r = (idx>>3)&31, c = idx&7;
            cpa16(st + 8192 + p*4608 + r*144 + c*16,
                  vp[p] + (size_t)(mk+r)*Cc + d0 + c*8);
        }
        CP_COMMIT();
    };

    load_stage(0, 0);
    load_stage(1, 32);
    CP_WAIT(1);
    __syncthreads();

    const int NKT = Nn/32;   // 72
    for (int kt = 0; kt < NKT; ++kt) {
        const int s = kt % 3;
        if (kt + 2 < NKT) load_stage((kt+2)%3, (kt+2)*32);

        const uint32_t st = base + s*AV_STAGE;
        #pragma unroll
        for (int ks=0; ks<32; ks+=16) {
            uint32_t a[2][4];
            #pragma unroll
            for (int mf=0; mf<2; ++mf) {
                int r = wm*32 + mf*16 + (lane&15);
                int c16 = (ks>>3) + (lane>>4);
                ldsm4(a[mf], sw64(st, r, c16));
            }
            #pragma unroll
            for (int nf2=0; nf2<2; ++nf2) {
                int cb = wn*32 + nf2*16;
                uint32_t bvr[4], bvi[4];
                uint32_t vaddr = st + 8192 + (uint32_t)(ks + (lane&15))*144 + (uint32_t)(cb + (lane>>4)*8)*2;
                ldsm4t(bvr, vaddr);
                ldsm4t(bvi, vaddr + 4608);
                #pragma unroll
                for (int h=0; h<2; ++h) {
                    int nfr = nf2*2 + h;
                    #pragma unroll
                    for (int mf=0; mf<2; ++mf) {
                        mma16(accr[mf][nfr], a[mf], bvr + 2*h);
                        mma16(acci[mf][nfr], a[mf], bvi + 2*h);
                    }
                }
            }
        }
        if (kt + 2 < NKT) { CP_WAIT(1); } else if (kt + 1 < NKT) { CP_WAIT(0); }
        __syncthreads();
    }

    // transpose epilogue -> g_outT [d][n] fp32 (smem reuse)
    float (*stage)[129] = (float(*)[129])dyn;
    const size_t basep = (size_t)b*Cc*Nn + (size_t)d0*Nn + n0;
    #pragma unroll
    for (int p=0; p<2; ++p) {
        #pragma unroll
        for (int mf=0; mf<2; ++mf) {
            int rl = wm*32 + mf*16 + gr;
            #pragma unroll
            for (int nfr=0; nfr<4; ++nfr) {
                int cl = wn*32 + nfr*8 + 2*tg;
                float* acc = p ? acci[mf][nfr] : accr[mf][nfr];
                stage[cl  ][rl  ] = acc[0];
                stage[cl+1][rl  ] = acc[1];
                stage[cl  ][rl+8] = acc[2];
                stage[cl+1][rl+8] = acc[3];
            }
        }
        __syncthreads();
        #pragma unroll
        for (int t=0; t<32; ++t) {
            int idx = tid + 256*t; int nl = idx & 127, dl = idx >> 7;
            g_outT[p][basep + (size_t)dl*Nn + nl] = stage[dl][nl];
        }
        __syncthreads();
    }
}

// ---------------------------------------------------------------------------
// Kernel 5/6: BatchNorm
// ---------------------------------------------------------------------------
__global__ void __launch_bounds__(256) k_bnstats(
    const float* __restrict__ xr, const float* __restrict__ xi,
    const float* __restrict__ gamma)
{
    const int c = blockIdx.x, p = blockIdx.y;
    const int tid = threadIdx.x;
    const float* x = p ? xi : xr;
    const float* o = g_outT[p];
    const float g = gamma[0];

    float s = 0.f, ss = 0.f;
    for (int b = 0; b < Bb; ++b) {
        const int bb = b*Cc*Nn + c*Nn;
        for (int n = tid; n < Nn; n += 256) {
            float z = x[bb+n] + g*o[bb+n];
            s  += z;
            ss += z*z;
        }
    }
    __shared__ float rs[256], rss[256];
    rs[tid] = s; rss[tid] = ss; __syncthreads();
    #pragma unroll
    for (int st = 128; st > 0; st >>= 1) {
        if (tid < st) { rs[tid] += rs[tid+st]; rss[tid] += rss[tid+st]; }
        __syncthreads();
    }
    if (tid == 0) {
        const float inv_cnt = 1.f / (float)Mtot;
        float mean = rs[0] * inv_cnt;
        float var  = rss[0] * inv_cnt - mean*mean;
        g_mean[p][c] = mean;
        g_rstd[p][c] = rsqrtf(var + EPSf);
    }
}

__global__ void __launch_bounds__(256) k_bnapply(
    const float* __restrict__ xr, const float* __restrict__ xi,
    const float* __restrict__ gamma,
    const float* __restrict__ bnwr, const float* __restrict__ bnbr,
    const float* __restrict__ bnwi, const float* __restrict__ bnbi,
    float* __restrict__ out)
{
    const int idx = blockIdx.x*256 + threadIdx.x;
    const int half = Bb*Cc*Nn;
    const int p = idx / half;
    const int rem = idx - p*half;
    const int c = (rem / Nn) % Cc;

    const float* x = p ? xi : xr;
    const float g = gamma[0];
    const float z = x[rem] + g*g_outT[p][rem];
    const float w = p ? bnwi[c] : bnwr[c];
    const float bia = p ? bnbi[c] : bnbr[c];
    out[idx] = (z - g_mean[p][c]) * g_rstd[p][c] * w + bia;
}

// ---------------------------------------------------------------------------
// Launch
// ---------------------------------------------------------------------------
extern "C" void kernel_launch(void* const* d_in, const int* in_sizes, int n_in,
                              void* d_out, int out_size)
{
    const float* xr   = (const float*)d_in[0];
    const float* xi   = (const float*)d_in[1];
    const float* q_wr = (const float*)d_in[2];
    const float* q_wi = (const float*)d_in[3];
    const float* q_br = (const float*)d_in[4];
    const float* q_bi = (const float*)d_in[5];
    const float* k_wr = (const float*)d_in[6];
    const float* k_wi = (const float*)d_in[7];
    const float* k_br = (const float*)d_in[8];
    const float* k_bi = (const float*)d_in[9];
    const float* v_wr = (const float*)d_in[10];
    const float* v_wi = (const float*)d_in[11];
    const float* v_br = (const float*)d_in[12];
    const float* v_bi = (const float*)d_in[13];
    const float* gamma= (const float*)d_in[14];
    const float* bnwr = (const float*)d_in[15];
    const float* bnbr = (const float*)d_in[16];
    const float* bnwi = (const float*)d_in[17];
    const float* bnbi = (const float*)d_in[18];
    float* out = (float*)d_out;

    cudaFuncSetAttribute(k_scores, cudaFuncAttributeMaxDynamicSharedMemorySize, SC_SMEM);
    cudaFuncSetAttribute(k_av,     cudaFuncAttributeMaxDynamicSharedMemorySize, AV_SMEM);

    k_proj<0><<<dim3(Mtot/128, Cc/64), 256>>>(xr, xi, q_wr, q_wi, q_br, q_bi);
    k_proj<1><<<dim3(Mtot/128, Cc/64), 256>>>(xr, xi, k_wr, k_wi, k_br, k_bi);
    k_proj<2><<<dim3(Mtot/128, Cc/64), 256>>>(xr, xi, v_wr, v_wi, v_br, v_bi);

    k_scores<<<dim3(Nn/128, Nn/128, Bb), 256, SC_SMEM>>>();
    k_softmax<<<Mtot, 256>>>();
    k_av<<<dim3(Nn/128, Cc/64, Bb), 256, AV_SMEM>>>();

    k_bnstats<<<dim3(Cc, 2), 256>>>(xr, xi, gamma);
    k_bnapply<<<(2*Bb*Cc*Nn)/256, 256>>>(xr, xi, gamma, bnwr, bnbr, bnwi, bnbi, out);
}

// round 6
// speedup vs baseline: 7.9528x; 1.1866x over previous
#include <cuda_runtime.h>
#include <cuda_bf16.h>
#include <math.h>
#include <stdint.h>

#define Bb   8
#define Cc   256
#define Nn   2304
#define Mtot (Bb*Nn)
#define EPSf 1e-5f

// ---------------------------------------------------------------------------
// Scratch
// ---------------------------------------------------------------------------
__device__ __align__(128) __nv_bfloat16 g_q[2][(size_t)Mtot*Cc];
__device__ __align__(128) __nv_bfloat16 g_k[2][(size_t)Mtot*Cc];
__device__ __align__(128) __nv_bfloat16 g_v[2][(size_t)Mtot*Cc];
__device__ __align__(128) __nv_bfloat16 g_attn [(size_t)Bb*Nn*Nn];   // bf16 logits
__device__ __align__(128) __nv_bfloat16 g_attnb[(size_t)Bb*Nn*Nn];   // bf16 probs
__device__ __align__(128) __nv_bfloat16 g_outT[2][(size_t)Bb*Cc*Nn]; // bf16 [p][b][c][n]
__device__ float g_mean[2][Cc];
__device__ float g_rstd[2][Cc];

// ---------------------------------------------------------------------------
// helpers
// ---------------------------------------------------------------------------
__device__ __forceinline__ uint32_t s2u(const void* p){
    return (uint32_t)__cvta_generic_to_shared(p);
}
__device__ __forceinline__ uint32_t packbf(float lo, float hi){
    uint32_t r;
    asm("cvt.rn.bf16x2.f32 %0, %1, %2;" : "=r"(r) : "f"(hi), "f"(lo));
    return r;
}
__device__ __forceinline__ void mma16(float* d, const uint32_t* a, const uint32_t* b){
    asm volatile("mma.sync.aligned.m16n8k16.row.col.f32.bf16.bf16.f32 "
        "{%0,%1,%2,%3}, {%4,%5,%6,%7}, {%8,%9}, {%0,%1,%2,%3};"
        : "+f"(d[0]),"+f"(d[1]),"+f"(d[2]),"+f"(d[3])
        : "r"(a[0]),"r"(a[1]),"r"(a[2]),"r"(a[3]),"r"(b[0]),"r"(b[1]));
}
__device__ __forceinline__ void ldsm4(uint32_t* r, uint32_t addr){
    asm volatile("ldmatrix.sync.aligned.m8n8.x4.shared.b16 {%0,%1,%2,%3}, [%4];"
        : "=r"(r[0]),"=r"(r[1]),"=r"(r[2]),"=r"(r[3]) : "r"(addr));
}
__device__ __forceinline__ void ldsm4t(uint32_t* r, uint32_t addr){
    asm volatile("ldmatrix.sync.aligned.m8n8.x4.trans.shared.b16 {%0,%1,%2,%3}, [%4];"
        : "=r"(r[0]),"=r"(r[1]),"=r"(r[2]),"=r"(r[3]) : "r"(addr));
}
__device__ __forceinline__ void cpa16(uint32_t dst, const void* src){
    asm volatile("cp.async.cg.shared.global [%0], [%1], 16;" :: "r"(dst), "l"(src));
}
#define CP_COMMIT() asm volatile("cp.async.commit_group;")
#define CP_WAIT(N)  asm volatile("cp.async.wait_group %0;" :: "n"(N))

// 64B-row smem tile: swizzled 16B-chunk offset
__device__ __forceinline__ uint32_t sw64(uint32_t tile, int r, int c16){
    return tile + (uint32_t)r*64u + (uint32_t)((c16 ^ ((r>>1)&3))<<4);
}

// ---------------------------------------------------------------------------
// Kernel 1: complex projection (mma.sync bf16), fp32 in, bf16 out [m][c]
// ---------------------------------------------------------------------------
template<int WSEL>
__global__ void __launch_bounds__(256) k_proj(
    const float* __restrict__ xr, const float* __restrict__ xi,
    const float* __restrict__ wr, const float* __restrict__ wi,
    const float* __restrict__ brv, const float* __restrict__ biv)
{
    __nv_bfloat16* yr = (WSEL==0)?g_q[0]:(WSEL==1)?g_k[0]:g_v[0];
    __nv_bfloat16* yi = (WSEL==0)?g_q[1]:(WSEL==1)?g_k[1]:g_v[1];

    __shared__ __nv_bfloat16 sX[2][16][136];   // [part][k][m]
    __shared__ __nv_bfloat16 sW[2][64][24];    // [part][d][k]

    const int tid = threadIdx.x;
    const int w = tid >> 5, lane = tid & 31;
    const int gr = lane >> 2, tg = lane & 3;
    const int wm = w & 3, wn = w >> 2;
    const int m0 = blockIdx.x * 128;
    const int d0 = blockIdx.y * 64;
    const int b  = m0 / Nn;
    const int n0 = m0 - b*Nn;

    const int lp = tid >> 7;
    const int lt = tid & 127;

    float accr[2][4][4], acci[2][4][4];
    #pragma unroll
    for (int mf=0; mf<2; ++mf)
        #pragma unroll
        for (int nf=0; nf<4; ++nf)
            #pragma unroll
            for (int e=0; e<4; ++e){ accr[mf][nf][e]=0.f; acci[mf][nf][e]=0.f; }

    for (int kt = 0; kt < Cc/16; ++kt) {
        const int ck = kt*16;
        const float* xs = lp ? xi : xr;
        const float* ws = lp ? wi : wr;
        #pragma unroll
        for (int it=0; it<4; ++it) {
            int idx = lt + 128*it;
            int c = idx >> 5, nq = idx & 31;
            const float4 v = *(const float4*)(xs + (size_t)b*Cc*Nn + (size_t)(ck+c)*Nn + n0 + nq*4);
            uint2 pk = make_uint2(packbf(v.x,v.y), packbf(v.z,v.w));
            *(uint2*)&sX[lp][c][nq*4] = pk;
        }
        #pragma unroll
        for (int it=0; it<2; ++it) {
            int idx = lt + 128*it;
            int d = idx >> 2, cq = idx & 3;
            const float4 v = *(const float4*)(ws + (size_t)(d0+d)*Cc + ck + cq*4);
            uint2 pk = make_uint2(packbf(v.x,v.y), packbf(v.z,v.w));
            *(uint2*)&sW[lp][d][cq*4] = pk;
        }
        __syncthreads();

        uint32_t axr[2][4], axi[2][4], ain[2][4];
        #pragma unroll
        for (int mf=0; mf<2; ++mf) {
            int rb = wm*32 + mf*16;
            ldsm4t(axr[mf], s2u(&sX[0][(lane&7) + (lane>>4)*8][rb + ((lane>>3)&1)*8]));
            ldsm4t(axi[mf], s2u(&sX[1][(lane&7) + (lane>>4)*8][rb + ((lane>>3)&1)*8]));
            #pragma unroll
            for (int e=0;e<4;++e) ain[mf][e] = axi[mf][e] ^ 0x80008000u;
        }
        #pragma unroll
        for (int nf2=0; nf2<2; ++nf2) {
            int cb = wn*32 + nf2*16;
            uint32_t bwr[4], bwi[4];
            ldsm4(bwr, s2u(&sW[0][cb + (lane>>4)*8 + (lane&7)][((lane>>3)&1)*8]));
            ldsm4(bwi, s2u(&sW[1][cb + (lane>>4)*8 + (lane&7)][((lane>>3)&1)*8]));
            #pragma unroll
            for (int h=0; h<2; ++h) {
                int nfr = nf2*2 + h;
                #pragma unroll
                for (int mf=0; mf<2; ++mf) {
                    mma16(accr[mf][nfr], axr[mf], bwr + 2*h);
                    mma16(accr[mf][nfr], ain[mf], bwi + 2*h);
                    mma16(acci[mf][nfr], axr[mf], bwi + 2*h);
                    mma16(acci[mf][nfr], axi[mf], bwr + 2*h);
                }
            }
        }
        __syncthreads();
    }

    #pragma unroll
    for (int mf=0; mf<2; ++mf) {
        const int row0 = m0 + wm*32 + mf*16 + gr;
        #pragma unroll
        for (int nfr=0; nfr<4; ++nfr) {
            const int col0 = d0 + wn*32 + nfr*8 + 2*tg;
            const float b0r = brv[col0], b1r = brv[col0+1];
            const float b0i = biv[col0], b1i = biv[col0+1];
            *(uint32_t*)&yr[(size_t)row0*Cc + col0]     = packbf(accr[mf][nfr][0]+b0r, accr[mf][nfr][1]+b1r);
            *(uint32_t*)&yr[(size_t)(row0+8)*Cc + col0] = packbf(accr[mf][nfr][2]+b0r, accr[mf][nfr][3]+b1r);
            *(uint32_t*)&yi[(size_t)row0*Cc + col0]     = packbf(acci[mf][nfr][0]+b0i, acci[mf][nfr][1]+b1i);
            *(uint32_t*)&yi[(size_t)(row0+8)*Cc + col0] = packbf(acci[mf][nfr][2]+b0i, acci[mf][nfr][3]+b1i);
        }
    }
}

// ---------------------------------------------------------------------------
// Kernel 2: scores. Block 128n x 128m, warps 2(n)x4(m), warp 64x32.
//   3-stage cp.async ring, K-step 32 per stage. bf16 logit output.
// ---------------------------------------------------------------------------
#define SC_STAGE 32768
#define SC_SMEM  (3*SC_STAGE)

__global__ void __launch_bounds__(256) k_scores()
{
    extern __shared__ __align__(16) unsigned char dyn[];
    const uint32_t base = s2u(dyn);

    const int tid = threadIdx.x;
    const int w = tid >> 5, lane = tid & 31;
    const int gr = lane >> 2, tg = lane & 3;
    const int wrow = w & 1, wcol = w >> 1;
    const int m0 = blockIdx.x * 128;
    const int n0 = blockIdx.y * 128;
    const int b  = blockIdx.z;

    const __nv_bfloat16* srcs[4] = {
        g_q[0] + (size_t)b*Nn*Cc, g_q[1] + (size_t)b*Nn*Cc,
        g_k[0] + (size_t)b*Nn*Cc, g_k[1] + (size_t)b*Nn*Cc };
    const int rbase[4] = { n0, n0, m0, m0 };

    float acc[4][4][4];
    #pragma unroll
    for (int mf=0; mf<4; ++mf)
        #pragma unroll
        for (int nf=0; nf<4; ++nf)
            #pragma unroll
            for (int e=0; e<4; ++e) acc[mf][nf][e]=0.f;

    auto load_stage = [&](int s, int ck){
        const uint32_t st = base + s*SC_STAGE;
        #pragma unroll
        for (int t=0;t<4;++t){
            const uint32_t tb = st + t*8192;
            #pragma unroll
            for (int it=0; it<2; ++it){
                int idx = tid + 256*it;
                int r = idx>>2, c = idx&3;
                cpa16(sw64(tb, r, c), srcs[t] + (size_t)(rbase[t]+r)*Cc + ck + c*8);
            }
        }
        CP_COMMIT();
    };

    load_stage(0, 0);
    load_stage(1, 32);

    for (int kt = 0; kt < 8; ++kt) {
        const int s = kt % 3;
        if (kt < 7) { CP_WAIT(1); } else { CP_WAIT(0); }
        __syncthreads();
        if (kt + 2 < 8) load_stage((kt+2)%3, (kt+2)*32);

        const uint32_t st = base + s*SC_STAGE;
        #pragma unroll
        for (int p=0; p<2; ++p) {
            const uint32_t qt = st + p*8192;
            const uint32_t ktile = st + 16384 + p*8192;
            #pragma unroll
            for (int ks=0; ks<32; ks+=16) {
                uint32_t a[4][4];
                #pragma unroll
                for (int mf=0; mf<4; ++mf) {
                    int r = wrow*64 + mf*16 + (lane&15);
                    int c16 = (ks>>3) + (lane>>4);
                    ldsm4(a[mf], sw64(qt, r, c16));
                }
                #pragma unroll
                for (int nf2=0; nf2<2; ++nf2) {
                    int rr = wcol*32 + nf2*16 + (lane>>4)*8 + (lane&7);
                    int c16 = (ks>>3) + ((lane>>3)&1);
                    uint32_t bb[4];
                    ldsm4(bb, sw64(ktile, rr, c16));
                    #pragma unroll
                    for (int mf=0; mf<4; ++mf) {
                        mma16(acc[mf][nf2*2  ], a[mf], bb);
                        mma16(acc[mf][nf2*2+1], a[mf], bb+2);
                    }
                }
            }
        }
        __syncthreads();
    }

    const float sc = 1.0f/16.0f;
    #pragma unroll
    for (int mf=0; mf<4; ++mf) {
        const int row0 = n0 + wrow*64 + mf*16 + gr;
        const size_t r0b = (size_t)b*Nn*Nn + (size_t)row0*Nn;
        const size_t r1b = r0b + (size_t)8*Nn;
        #pragma unroll
        for (int nfr=0; nfr<4; ++nfr) {
            const int col0 = m0 + wcol*32 + nfr*8 + 2*tg;
            *(uint32_t*)&g_attn[r0b + col0] = packbf(acc[mf][nfr][0]*sc, acc[mf][nfr][1]*sc);
            *(uint32_t*)&g_attn[r1b + col0] = packbf(acc[mf][nfr][2]*sc, acc[mf][nfr][3]*sc);
        }
    }
}

// ---------------------------------------------------------------------------
// Kernel 3: softmax — bf16 logits in, bf16 probs out. 384 thr, 6 elems each.
// ---------------------------------------------------------------------------
__global__ void __launch_bounds__(384) k_softmax()
{
    const size_t rowbase = (size_t)blockIdx.x * Nn;
    const __nv_bfloat162* src = (const __nv_bfloat162*)(g_attn + rowbase);
    __nv_bfloat162* dst = (__nv_bfloat162*)(g_attnb + rowbase);
    const int tid = threadIdx.x;
    const int wid = tid >> 5, lane = tid & 31;

    __shared__ float sred[12];
    __shared__ float sbc;

    float v[6];
    #pragma unroll
    for (int i=0;i<3;++i){
        float2 f = __bfloat1622float2(src[tid + 384*i]);
        v[2*i] = f.x; v[2*i+1] = f.y;
    }
    float mx = v[0];
    #pragma unroll
    for (int i=1;i<6;++i) mx = fmaxf(mx, v[i]);
    #pragma unroll
    for (int off=16; off>0; off>>=1) mx = fmaxf(mx, __shfl_xor_sync(0xFFFFFFFFu, mx, off));
    if (lane==0) sred[wid] = mx;
    __syncthreads();
    if (wid==0){
        float m2 = (lane<12) ? sred[lane] : -1e30f;
        #pragma unroll
        for (int off=8; off>0; off>>=1) m2 = fmaxf(m2, __shfl_xor_sync(0xFFFFFFFFu, m2, off));
        if (lane==0) sbc = m2;
    }
    __syncthreads();
    mx = sbc;

    float sum = 0.f;
    #pragma unroll
    for (int i=0;i<6;++i){ v[i] = __expf(v[i]-mx); sum += v[i]; }
    #pragma unroll
    for (int off=16; off>0; off>>=1) sum += __shfl_xor_sync(0xFFFFFFFFu, sum, off);
    if (lane==0) sred[wid] = sum;
    __syncthreads();
    if (wid==0){
        float s2 = (lane<12) ? sred[lane] : 0.f;
        #pragma unroll
        for (int off=8; off>0; off>>=1) s2 += __shfl_xor_sync(0xFFFFFFFFu, s2, off);
        if (lane==0) sbc = s2;
    }
    __syncthreads();
    const float inv = 1.f / sbc;

    #pragma unroll
    for (int i=0;i<3;++i)
        dst[tid + 384*i] = __float22bfloat162_rn(make_float2(v[2*i]*inv, v[2*i+1]*inv));
}

// ---------------------------------------------------------------------------
// Kernel 4: AV. Block 128n x 64d, warps 4(n)x2(d). 4-stage ring, K-step 32.
//   Output bf16 [d][n] via smem transpose stage.
// ---------------------------------------------------------------------------
#define AV_STAGE 17408
#define AV_SMEM  (4*AV_STAGE)

__global__ void __launch_bounds__(256) k_av()
{
    extern __shared__ __align__(16) unsigned char dyn[];
    const uint32_t base = s2u(dyn);

    const int tid = threadIdx.x;
    const int w = tid >> 5, lane = tid & 31;
    const int gr = lane >> 2, tg = lane & 3;
    const int wm = w & 3, wn = w >> 2;
    const int n0 = blockIdx.x * 128;
    const int d0 = blockIdx.y * 64;
    const int b  = blockIdx.z;

    const __nv_bfloat16* Ab  = g_attnb + (size_t)b*Nn*Nn;
    const __nv_bfloat16* vp[2] = { g_v[0] + (size_t)b*Nn*Cc, g_v[1] + (size_t)b*Nn*Cc };

    float accr[2][4][4], acci[2][4][4];
    #pragma unroll
    for (int mf=0; mf<2; ++mf)
        #pragma unroll
        for (int nf=0; nf<4; ++nf)
            #pragma unroll
            for (int e=0; e<4; ++e){ accr[mf][nf][e]=0.f; acci[mf][nf][e]=0.f; }

    auto load_stage = [&](int s, int mk){
        const uint32_t st = base + s*AV_STAGE;
        #pragma unroll
        for (int it=0; it<2; ++it){
            int idx = tid + 256*it;
            int r = idx>>2, c = idx&3;
            cpa16(sw64(st, r, c), Ab + (size_t)(n0+r)*Nn + mk + c*8);
        }
        #pragma unroll
        for (int it=0; it<2; ++it){
            int idx = tid + 256*it;
            int p = idx>>8, r = (idx>>3)&31, c = idx&7;
            cpa16(st + 8192 + p*4608 + r*144 + c*16,
                  vp[p] + (size_t)(mk+r)*Cc + d0 + c*8);
        }
        CP_COMMIT();
    };

    load_stage(0, 0);
    load_stage(1, 32);
    load_stage(2, 64);

    const int NKT = Nn/32;   // 72
    for (int kt = 0; kt < NKT; ++kt) {
        const int s = kt & 3;
        if (kt < NKT-2)      { CP_WAIT(2); }
        else if (kt == NKT-2){ CP_WAIT(1); }
        else                 { CP_WAIT(0); }
        __syncthreads();
        if (kt + 3 < NKT) load_stage((kt+3)&3, (kt+3)*32);

        const uint32_t st = base + s*AV_STAGE;
        #pragma unroll
        for (int ks=0; ks<32; ks+=16) {
            uint32_t a[2][4];
            #pragma unroll
            for (int mf=0; mf<2; ++mf) {
                int r = wm*32 + mf*16 + (lane&15);
                int c16 = (ks>>3) + (lane>>4);
                ldsm4(a[mf], sw64(st, r, c16));
            }
            #pragma unroll
            for (int nf2=0; nf2<2; ++nf2) {
                int cb = wn*32 + nf2*16;
                uint32_t bvr[4], bvi[4];
                uint32_t vaddr = st + 8192 + (uint32_t)(ks + (lane&15))*144 + (uint32_t)(cb + (lane>>4)*8)*2;
                ldsm4t(bvr, vaddr);
                ldsm4t(bvi, vaddr + 4608);
                #pragma unroll
                for (int h=0; h<2; ++h) {
                    int nfr = nf2*2 + h;
                    #pragma unroll
                    for (int mf=0; mf<2; ++mf) {
                        mma16(accr[mf][nfr], a[mf], bvr + 2*h);
                        mma16(acci[mf][nfr], a[mf], bvi + 2*h);
                    }
                }
            }
        }
        __syncthreads();
    }

    // transpose epilogue -> g_outT [d][n] bf16 (smem reuse)
    __nv_bfloat16 (*stage)[144] = (__nv_bfloat16(*)[144])dyn;
    const size_t basep = (size_t)b*Cc*Nn + (size_t)d0*Nn + n0;
    #pragma unroll
    for (int p=0; p<2; ++p) {
        __syncthreads();
        #pragma unroll
        for (int mf=0; mf<2; ++mf) {
            int rl = wm*32 + mf*16 + gr;
            #pragma unroll
            for (int nfr=0; nfr<4; ++nfr) {
                int cl = wn*32 + nfr*8 + 2*tg;
                float* acc = p ? acci[mf][nfr] : accr[mf][nfr];
                stage[cl  ][rl  ] = __float2bfloat16(acc[0]);
                stage[cl+1][rl  ] = __float2bfloat16(acc[1]);
                stage[cl  ][rl+8] = __float2bfloat16(acc[2]);
                stage[cl+1][rl+8] = __float2bfloat16(acc[3]);
            }
        }
        __syncthreads();
        #pragma unroll
        for (int it=0; it<4; ++it) {
            int idx = tid + 256*it;          // 1024 x uint4 over 64x128
            int dl = idx >> 4, c8 = idx & 15;
            *(uint4*)(g_outT[p] + basep + (size_t)dl*Nn + c8*8) = *(const uint4*)&stage[dl][c8*8];
        }
    }
}

// ---------------------------------------------------------------------------
// Kernel 5/6: BatchNorm (bf16 outT, vectorized)
// ---------------------------------------------------------------------------
__global__ void __launch_bounds__(256) k_bnstats(
    const float* __restrict__ xr, const float* __restrict__ xi,
    const float* __restrict__ gamma)
{
    const int c = blockIdx.x, p = blockIdx.y;
    const int tid = threadIdx.x;
    const float* x = p ? xi : xr;
    const __nv_bfloat16* o = g_outT[p];
    const float g = gamma[0];

    float s = 0.f, ss = 0.f;
    for (int b = 0; b < Bb; ++b) {
        const size_t bb = (size_t)b*Cc*Nn + (size_t)c*Nn;
        for (int n4 = tid; n4 < Nn/4; n4 += 256) {
            float4 xv = *(const float4*)(x + bb + n4*4);
            uint2 ou = *(const uint2*)(o + bb + n4*4);
            float2 o01 = __bfloat1622float2(*reinterpret_cast<const __nv_bfloat162*>(&ou.x));
            float2 o23 = __bfloat1622float2(*reinterpret_cast<const __nv_bfloat162*>(&ou.y));
            float z0 = xv.x + g*o01.x, z1 = xv.y + g*o01.y;
            float z2 = xv.z + g*o23.x, z3 = xv.w + g*o23.y;
            s  += z0+z1+z2+z3;
            ss += z0*z0+z1*z1+z2*z2+z3*z3;
        }
    }
    __shared__ float rs[256], rss[256];
    rs[tid] = s; rss[tid] = ss; __syncthreads();
    #pragma unroll
    for (int st = 128; st > 0; st >>= 1) {
        if (tid < st) { rs[tid] += rs[tid+st]; rss[tid] += rss[tid+st]; }
        __syncthreads();
    }
    if (tid == 0) {
        const float inv_cnt = 1.f / (float)Mtot;
        float mean = rs[0] * inv_cnt;
        float var  = rss[0] * inv_cnt - mean*mean;
        g_mean[p][c] = mean;
        g_rstd[p][c] = rsqrtf(var + EPSf);
    }
}

__global__ void __launch_bounds__(256) k_bnapply(
    const float* __restrict__ xr, const float* __restrict__ xi,
    const float* __restrict__ gamma,
    const float* __restrict__ bnwr, const float* __restrict__ bnbr,
    const float* __restrict__ bnwi, const float* __restrict__ bnbi,
    float* __restrict__ out)
{
    const int idx4 = blockIdx.x*256 + threadIdx.x;
    const size_t e = (size_t)idx4 * 4;
    const size_t half = (size_t)Bb*Cc*Nn;
    const int p = (e >= half) ? 1 : 0;
    const size_t rem = e - (size_t)p*half;
    const int c = (int)((rem / Nn) % Cc);

    const float* x = p ? xi : xr;
    const float g = gamma[0];
    const float wsc = (p ? bnwi[c] : bnwr[c]) * g_rstd[p][c];
    const float bia = (p ? bnbi[c] : bnbr[c]);
    const float mu = g_mean[p][c];

    float4 xv = *(const float4*)(x + rem);
    uint2 ou = *(const uint2*)(g_outT[p] + rem);
    float2 o01 = __bfloat1622float2(*reinterpret_cast<const __nv_bfloat162*>(&ou.x));
    float2 o23 = __bfloat1622float2(*reinterpret_cast<const __nv_bfloat162*>(&ou.y));

    float4 r;
    r.x = (xv.x + g*o01.x - mu) * wsc + bia;
    r.y = (xv.y + g*o01.y - mu) * wsc + bia;
    r.z = (xv.z + g*o23.x - mu) * wsc + bia;
    r.w = (xv.w + g*o23.y - mu) * wsc + bia;
    *(float4*)(out + e) = r;
}

// ---------------------------------------------------------------------------
// Launch
// ---------------------------------------------------------------------------
extern "C" void kernel_launch(void* const* d_in, const int* in_sizes, int n_in,
                              void* d_out, int out_size)
{
    const float* xr   = (const float*)d_in[0];
    const float* xi   = (const float*)d_in[1];
    const float* q_wr = (const float*)d_in[2];
    const float* q_wi = (const float*)d_in[3];
    const float* q_br = (const float*)d_in[4];
    const float* q_bi = (const float*)d_in[5];
    const float* k_wr = (const float*)d_in[6];
    const float* k_wi = (const float*)d_in[7];
    const float* k_br = (const float*)d_in[8];
    const float* k_bi = (const float*)d_in[9];
    const float* v_wr = (const float*)d_in[10];
    const float* v_wi = (const float*)d_in[11];
    const float* v_br = (const float*)d_in[12];
    const float* v_bi = (const float*)d_in[13];
    const float* gamma= (const float*)d_in[14];
    const float* bnwr = (const float*)d_in[15];
    const float* bnbr = (const float*)d_in[16];
    const float* bnwi = (const float*)d_in[17];
    const float* bnbi = (const float*)d_in[18];
    float* out = (float*)d_out;

    cudaFuncSetAttribute(k_scores, cudaFuncAttributeMaxDynamicSharedMemorySize, SC_SMEM);
    cudaFuncSetAttribute(k_av,     cudaFuncAttributeMaxDynamicSharedMemorySize, AV_SMEM);

    k_proj<0><<<dim3(Mtot/128, Cc/64), 256>>>(xr, xi, q_wr, q_wi, q_br, q_bi);
    k_proj<1><<<dim3(Mtot/128, Cc/64), 256>>>(xr, xi, k_wr, k_wi, k_br, k_bi);
    k_proj<2><<<dim3(Mtot/128, Cc/64), 256>>>(xr, xi, v_wr, v_wi, v_br, v_bi);

    k_scores<<<dim3(Nn/128, Nn/128, Bb), 256, SC_SMEM>>>();
    k_softmax<<<Mtot, 384>>>();
    k_av<<<dim3(Nn/128, Cc/64, Bb), 256, AV_SMEM>>>();

    k_bnstats<<<dim3(Cc, 2), 256>>>(xr, xi, gamma);
    k_bnapply<<<(2*(size_t)Bb*Cc*Nn/4)/256, 256>>>(xr, xi, gamma, bnwr, bnbr, bnwi, bnbi, out);
}